// round 1
// baseline (speedup 1.0000x reference)
#include <cuda_runtime.h>
#include <cuda_bf16.h>
#include <cstdint>

// ---------------------------------------------------------------------------
// MultiHeadAttention: out = softmax((XQ Wq^T)(XK Wk^T)^T * 64) (XV Wv^T)
// b=2, s=2048, d=1024, heads=16, hd=64. All fp32 (precision required: scores
// have std ~170 -> softmax is quasi-argmax; low precision flips argmax rows).
// ---------------------------------------------------------------------------

#define BATCH     2
#define SEQ       2048
#define DMODEL    1024
#define NHEADS    16
#define HDIM      64
#define NEG_INF   (-3.0e38f)

// Scratch for head-split projections: [b][h][s][hd]
__device__ float g_Qh[BATCH * NHEADS * SEQ * HDIM];
__device__ float g_Kh[BATCH * NHEADS * SEQ * HDIM];
__device__ float g_Vh[BATCH * NHEADS * SEQ * HDIM];

// ---------------------------------------------------------------------------
// Projection GEMM: Out[m,n] = sum_k X[m,k] * W[n,k]   (NT, fp32)
// M=4096, N=1024, K=1024. Tile 128x128x16, 256 threads, 8x8 per thread.
// Epilogue writes head-split layout [b][h][s][hd].
// ---------------------------------------------------------------------------
#define PBK 16
#define PLD 132   // padded leading dim (132*4B=528B, 16B-aligned per row)

__global__ __launch_bounds__(256, 2)
void proj_kernel(const float* __restrict__ X, const float* __restrict__ W,
                 float* __restrict__ Out)
{
    __shared__ float As[PBK][PLD];   // [k][m]
    __shared__ float Bs[PBK][PLD];   // [k][n]

    const int m0 = blockIdx.x * 128;
    const int n0 = blockIdx.y * 128;
    const int tid = threadIdx.x;
    const int ty = tid >> 4;         // 0..15
    const int tx = tid & 15;         // 0..15

    float acc[8][8];
#pragma unroll
    for (int i = 0; i < 8; i++)
#pragma unroll
        for (int j = 0; j < 8; j++) acc[i][j] = 0.f;

    for (int k0 = 0; k0 < DMODEL; k0 += PBK) {
        // Load A tile: 128 rows x 16 k = 512 float4, 2 per thread
#pragma unroll
        for (int q = 0; q < 2; q++) {
            int lin = tid + q * 256;           // float4 index
            int row = lin >> 2;                // 0..127
            int kq  = (lin & 3) * 4;
            float4 v = *reinterpret_cast<const float4*>(
                &X[(size_t)(m0 + row) * DMODEL + k0 + kq]);
            As[kq + 0][row] = v.x; As[kq + 1][row] = v.y;
            As[kq + 2][row] = v.z; As[kq + 3][row] = v.w;
        }
#pragma unroll
        for (int q = 0; q < 2; q++) {
            int lin = tid + q * 256;
            int row = lin >> 2;
            int kq  = (lin & 3) * 4;
            float4 v = *reinterpret_cast<const float4*>(
                &W[(size_t)(n0 + row) * DMODEL + k0 + kq]);
            Bs[kq + 0][row] = v.x; Bs[kq + 1][row] = v.y;
            Bs[kq + 2][row] = v.z; Bs[kq + 3][row] = v.w;
        }
        __syncthreads();

#pragma unroll
        for (int kk = 0; kk < PBK; kk++) {
            float a[8], b[8];
            *reinterpret_cast<float4*>(&a[0]) =
                *reinterpret_cast<const float4*>(&As[kk][ty * 8]);
            *reinterpret_cast<float4*>(&a[4]) =
                *reinterpret_cast<const float4*>(&As[kk][ty * 8 + 4]);
            *reinterpret_cast<float4*>(&b[0]) =
                *reinterpret_cast<const float4*>(&Bs[kk][tx * 8]);
            *reinterpret_cast<float4*>(&b[4]) =
                *reinterpret_cast<const float4*>(&Bs[kk][tx * 8 + 4]);
#pragma unroll
            for (int i = 0; i < 8; i++)
#pragma unroll
                for (int j = 0; j < 8; j++)
                    acc[i][j] += a[i] * b[j];
        }
        __syncthreads();
    }

    // Epilogue: head-split layout. n-range tx*8..tx*8+7 stays within one head
    // for each half (hd = n&63, tx*8&63 <= 56).
    const int n_lo = n0 + tx * 8;
    const int h    = n_lo >> 6;
    const int hd0  = n_lo & 63;
#pragma unroll
    for (int i = 0; i < 8; i++) {
        int m = m0 + ty * 8 + i;
        int bb = m >> 11;
        int ss = m & 2047;
        float* dst = &Out[((size_t)(bb * NHEADS + h) * SEQ + ss) * HDIM + hd0];
        float4 v0 = make_float4(acc[i][0], acc[i][1], acc[i][2], acc[i][3]);
        float4 v1 = make_float4(acc[i][4], acc[i][5], acc[i][6], acc[i][7]);
        *reinterpret_cast<float4*>(dst)     = v0;
        *reinterpret_cast<float4*>(dst + 4) = v1;
    }
}

// ---------------------------------------------------------------------------
// Flash attention, fp32. One CTA per (q-tile of 64, head, batch).
// 256 threads, 4x4 output per thread. Online softmax with exp (scores already
// carry the x64 scale).
// Dynamic smem layout (floats):
//   Qs[64*64] (hd-major), Ks[64*64] (hd-major), Vs[64*64] (key-major),
//   Ss[64*64] (row-major), mrow[64], lrow[64], arow[64], pred[64*4]
// ---------------------------------------------------------------------------
#define ATTN_SMEM_FLOATS (4 * 4096 + 64 * 3 + 64 * 4)
#define ATTN_SMEM_BYTES  (ATTN_SMEM_FLOATS * 4)

__global__ __launch_bounds__(256, 2)
void attn_kernel(const float* __restrict__ Q, const float* __restrict__ K,
                 const float* __restrict__ V, float* __restrict__ Out)
{
    extern __shared__ float sm[];
    float* Qs   = sm;              // [hd][r]
    float* Ks   = sm + 4096;       // [hd][c]
    float* Vs   = sm + 8192;       // [k][hd]
    float* Ss   = sm + 12288;      // [r][k] -> P in place
    float* mrow = sm + 16384;
    float* lrow = mrow + 64;
    float* arow = lrow + 64;
    float* pred = arow + 64;       // [64][4] partial max / partial sum

    const int tid = threadIdx.x;
    const int ty = tid >> 4;
    const int tx = tid & 15;
    const int q0 = blockIdx.x * 64;
    const int h  = blockIdx.y;
    const int b  = blockIdx.z;
    const size_t base = (size_t)(b * NHEADS + h) * SEQ * HDIM;

    // Load Q tile (transposed to hd-major)
#pragma unroll
    for (int q = 0; q < 4; q++) {
        int lin = tid + q * 256;
        int r  = lin >> 4;               // 0..63
        int hd = (lin & 15) * 4;
        float4 v = *reinterpret_cast<const float4*>(
            &Q[base + (size_t)(q0 + r) * HDIM + hd]);
        Qs[(hd + 0) * 64 + r] = v.x; Qs[(hd + 1) * 64 + r] = v.y;
        Qs[(hd + 2) * 64 + r] = v.z; Qs[(hd + 3) * 64 + r] = v.w;
    }
    if (tid < 64) { mrow[tid] = NEG_INF; lrow[tid] = 0.f; }

    float o[4][4];
#pragma unroll
    for (int i = 0; i < 4; i++)
#pragma unroll
        for (int j = 0; j < 4; j++) o[i][j] = 0.f;

    for (int kt = 0; kt < SEQ; kt += 64) {
        __syncthreads();   // protect Ks/Vs/Ss (+ first-iter Qs/stat init)

        // Load K tile (hd-major), V tile (key-major)
#pragma unroll
        for (int q = 0; q < 4; q++) {
            int lin = tid + q * 256;
            int c  = lin >> 4;
            int hd = (lin & 15) * 4;
            float4 v = *reinterpret_cast<const float4*>(
                &K[base + (size_t)(kt + c) * HDIM + hd]);
            Ks[(hd + 0) * 64 + c] = v.x; Ks[(hd + 1) * 64 + c] = v.y;
            Ks[(hd + 2) * 64 + c] = v.z; Ks[(hd + 3) * 64 + c] = v.w;
        }
#pragma unroll
        for (int q = 0; q < 4; q++) {
            int lin = tid + q * 256;
            int kr = lin >> 4;
            int hd = (lin & 15) * 4;
            *reinterpret_cast<float4*>(&Vs[kr * 64 + hd]) =
                *reinterpret_cast<const float4*>(
                    &V[base + (size_t)(kt + kr) * HDIM + hd]);
        }
        __syncthreads();

        // S = (Q K^T) * 64
        float s[4][4];
#pragma unroll
        for (int i = 0; i < 4; i++)
#pragma unroll
            for (int j = 0; j < 4; j++) s[i][j] = 0.f;
#pragma unroll
        for (int kk = 0; kk < 64; kk++) {
            float a[4], bb[4];
            *reinterpret_cast<float4*>(a) =
                *reinterpret_cast<const float4*>(&Qs[kk * 64 + ty * 4]);
            *reinterpret_cast<float4*>(bb) =
                *reinterpret_cast<const float4*>(&Ks[kk * 64 + tx * 4]);
#pragma unroll
            for (int i = 0; i < 4; i++)
#pragma unroll
                for (int j = 0; j < 4; j++)
                    s[i][j] += a[i] * bb[j];
        }
#pragma unroll
        for (int i = 0; i < 4; i++) {
            float4 st = make_float4(s[i][0] * 64.f, s[i][1] * 64.f,
                                    s[i][2] * 64.f, s[i][3] * 64.f);
            *reinterpret_cast<float4*>(&Ss[(ty * 4 + i) * 64 + tx * 4]) = st;
        }
        __syncthreads();

        // Partial row max: thread -> (row = tid>>2, chunk = tid&3, 16 elems)
        {
            int r = tid >> 2, c = tid & 3;
            const float* row = &Ss[r * 64 + c * 16];
            float pm = NEG_INF;
#pragma unroll
            for (int e = 0; e < 16; e++) pm = fmaxf(pm, row[e]);
            pred[r * 4 + c] = pm;
        }
        __syncthreads();
        if (tid < 64) {
            int r = tid;
            float rm = fmaxf(fmaxf(pred[r * 4 + 0], pred[r * 4 + 1]),
                             fmaxf(pred[r * 4 + 2], pred[r * 4 + 3]));
            float mold = mrow[r];
            float mnew = fmaxf(mold, rm);
            float alpha = __expf(mold - mnew);   // 0 when mold = -inf
            mrow[r] = mnew;
            arow[r] = alpha;
            lrow[r] *= alpha;
        }
        __syncthreads();

        // P = exp(S - m) in place + partial sums
        {
            int r = tid >> 2, c = tid & 3;
            float mn = mrow[r];
            float* row = &Ss[r * 64 + c * 16];
            float ps = 0.f;
#pragma unroll
            for (int e = 0; e < 16; e++) {
                float p = __expf(row[e] - mn);
                row[e] = p;
                ps += p;
            }
            pred[r * 4 + c] = ps;
        }
        __syncthreads();
        if (tid < 64) {
            int r = tid;
            lrow[r] += pred[r * 4 + 0] + pred[r * 4 + 1] +
                       pred[r * 4 + 2] + pred[r * 4 + 3];
        }

        // Rescale O, accumulate O += P * V
        float al[4];
#pragma unroll
        for (int i = 0; i < 4; i++) al[i] = arow[ty * 4 + i];
#pragma unroll
        for (int i = 0; i < 4; i++)
#pragma unroll
            for (int j = 0; j < 4; j++) o[i][j] *= al[i];

#pragma unroll
        for (int kk = 0; kk < 64; kk++) {
            float p[4], vv[4];
#pragma unroll
            for (int i = 0; i < 4; i++)
                p[i] = Ss[(ty * 4 + i) * 64 + kk];
            *reinterpret_cast<float4*>(vv) =
                *reinterpret_cast<const float4*>(&Vs[kk * 64 + tx * 4]);
#pragma unroll
            for (int i = 0; i < 4; i++)
#pragma unroll
                for (int j = 0; j < 4; j++)
                    o[i][j] += p[i] * vv[j];
        }
    }
    __syncthreads();   // make final lrow visible to all

    // Normalize + write out[b][s][h*64+hd]
#pragma unroll
    for (int i = 0; i < 4; i++) {
        int sidx = q0 + ty * 4 + i;
        float linv = 1.f / lrow[ty * 4 + i];
        float4 ov = make_float4(o[i][0] * linv, o[i][1] * linv,
                                o[i][2] * linv, o[i][3] * linv);
        *reinterpret_cast<float4*>(
            &Out[((size_t)(b * SEQ + sidx) * NHEADS + h) * HDIM + tx * 4]) = ov;
    }
}

// ---------------------------------------------------------------------------
extern "C" void kernel_launch(void* const* d_in, const int* in_sizes, int n_in,
                              void* d_out, int out_size)
{
    const float* q  = (const float*)d_in[0];
    const float* k  = (const float*)d_in[1];
    const float* v  = (const float*)d_in[2];
    const float* Wq = (const float*)d_in[3];
    const float* Wk = (const float*)d_in[4];
    const float* Wv = (const float*)d_in[5];
    float* out = (float*)d_out;

    float *Qh, *Kh, *Vh;
    cudaGetSymbolAddress((void**)&Qh, g_Qh);
    cudaGetSymbolAddress((void**)&Kh, g_Kh);
    cudaGetSymbolAddress((void**)&Vh, g_Vh);

    cudaFuncSetAttribute(attn_kernel,
                         cudaFuncAttributeMaxDynamicSharedMemorySize,
                         ATTN_SMEM_BYTES);

    dim3 pg(BATCH * SEQ / 128, DMODEL / 128);   // (32, 8)
    proj_kernel<<<pg, 256>>>(q, Wq, Qh);
    proj_kernel<<<pg, 256>>>(k, Wk, Kh);
    proj_kernel<<<pg, 256>>>(v, Wv, Vh);

    dim3 ag(SEQ / 64, NHEADS, BATCH);           // (32, 16, 2)
    attn_kernel<<<ag, 256, ATTN_SMEM_BYTES>>>(Qh, Kh, Vh, out);
}

// round 3
// speedup vs baseline: 1.2673x; 1.2673x over previous
#include <cuda_runtime.h>
#include <cuda_bf16.h>
#include <cstdint>

// ---------------------------------------------------------------------------
// MultiHeadAttention: out = softmax((XQ Wq^T)(XK Wk^T)^T * 64) (XV Wv^T)
// b=2, s=2048, d=1024, heads=16, hd=64.
// Round 3: projections via warp-level mma.sync (HMMA, baseline ISA - tcgen05
// is blocked by the harness's sm_103 PTX target) with bf16x2 split:
// X*W ~= Xhi*Whi + Xlo*Whi + Xhi*Wlo, fp32 accum. Attention unchanged.
// ---------------------------------------------------------------------------

#define BATCH     2
#define SEQ       2048
#define DMODEL    1024
#define NHEADS    16
#define HDIM      64
#define NEG_INF   (-3.0e38f)

// Scratch: head-split projections [b][h][s][hd]
__device__ float g_Qh[BATCH * NHEADS * SEQ * HDIM];
__device__ float g_Kh[BATCH * NHEADS * SEQ * HDIM];
__device__ float g_Vh[BATCH * NHEADS * SEQ * HDIM];
// bf16x2 split operands
__device__ __nv_bfloat16 g_Xhi[3ull * 4096 * 1024];
__device__ __nv_bfloat16 g_Xlo[3ull * 4096 * 1024];
__device__ __nv_bfloat16 g_Whi[3ull * 1024 * 1024];
__device__ __nv_bfloat16 g_Wlo[3ull * 1024 * 1024];

__device__ __forceinline__ uint32_t smem_u32(const void* p) {
    uint32_t a;
    asm("{ .reg .u64 t; cvta.to.shared.u64 t, %1; cvt.u32.u64 %0, t; }"
        : "=r"(a) : "l"(p));
    return a;
}
__device__ __forceinline__ uint32_t sw128(uint32_t b) {
    return b ^ ((b >> 3) & 0x70);
}

#define LDSM_X4(r0, r1, r2, r3, addr) \
    asm volatile("ldmatrix.sync.aligned.m8n8.x4.shared.b16 {%0,%1,%2,%3}, [%4];" \
                 : "=r"(r0), "=r"(r1), "=r"(r2), "=r"(r3) : "r"(addr))

#define MMA_BF16(d, a, b0, b1) \
    asm volatile("mma.sync.aligned.m16n8k16.row.col.f32.bf16.bf16.f32 " \
                 "{%0,%1,%2,%3}, {%4,%5,%6,%7}, {%8,%9}, {%0,%1,%2,%3};" \
                 : "+f"((d)[0]), "+f"((d)[1]), "+f"((d)[2]), "+f"((d)[3]) \
                 : "r"((a)[0]), "r"((a)[1]), "r"((a)[2]), "r"((a)[3]), \
                   "r"(b0), "r"(b1))

// ===========================================================================
// Split kernel: x -> (bf16 hi, bf16 lo)
// ===========================================================================
__global__ void split_kernel(const float4* __restrict__ src,
                             __nv_bfloat16* __restrict__ hi,
                             __nv_bfloat16* __restrict__ lo, int n4)
{
    int i = blockIdx.x * 256 + threadIdx.x;
    if (i >= n4) return;
    float4 v = src[i];
    float xs[4] = {v.x, v.y, v.z, v.w};
    uint32_t hb[4], lb[4];
#pragma unroll
    for (int j = 0; j < 4; j++) {
        __nv_bfloat16 h = __float2bfloat16(xs[j]);
        __nv_bfloat16 l = __float2bfloat16(xs[j] - __bfloat162float(h));
        hb[j] = (uint32_t)__bfloat16_as_ushort(h);
        lb[j] = (uint32_t)__bfloat16_as_ushort(l);
    }
    uint2 hp, lp;
    hp.x = hb[0] | (hb[1] << 16); hp.y = hb[2] | (hb[3] << 16);
    lp.x = lb[0] | (lb[1] << 16); lp.y = lb[2] | (lb[3] << 16);
    reinterpret_cast<uint2*>(hi)[i] = hp;
    reinterpret_cast<uint2*>(lo)[i] = lp;
}

// ===========================================================================
// Projection GEMM via mma.sync: Out[m,n] = sum_k X[m,k] * W[n,k]
// M=4096, N=1024, K=1024; z selects (Q,K,V). CTA tile 128x128, K-chunk 64.
// 8 warps as 4(m) x 2(n); warp tile 32x64. bf16x2 split -> 3 HMMA per tile.
// SMEM: Ah/Al/Bh/Bl tiles, each 128 rows x 64 bf16 (128B rows, SW128).
// ===========================================================================
#define PROJ_SMEM (4 * 16384)

__device__ __forceinline__ void load_tile(const uint4* __restrict__ g,
                                          int row0, int ku4, char* smt, int tid)
{
#pragma unroll
    for (int q = 0; q < 4; q++) {
        int lin = tid + q * 256;
        int row = lin >> 3, col = lin & 7;
        uint4 v = g[(size_t)(row0 + row) * 128 + ku4 + col];
        *reinterpret_cast<uint4*>(smt + sw128(row * 128 + col * 16)) = v;
    }
}

__global__ __launch_bounds__(256, 2)
void proj_mma_kernel(const __nv_bfloat16* __restrict__ Xhi_all,
                     const __nv_bfloat16* __restrict__ Xlo_all,
                     const __nv_bfloat16* __restrict__ Whi_all,
                     const __nv_bfloat16* __restrict__ Wlo_all,
                     float* __restrict__ Qh, float* __restrict__ Kh,
                     float* __restrict__ Vh)
{
    extern __shared__ char smp[];
    char* Ah = smp;
    char* Al = smp + 16384;
    char* Bh = smp + 32768;
    char* Bl = smp + 49152;
    const uint32_t ah_u = smem_u32(Ah), al_u = smem_u32(Al);
    const uint32_t bh_u = smem_u32(Bh), bl_u = smem_u32(Bl);

    const int tid  = threadIdx.x;
    const int wid  = tid >> 5, lane = tid & 31;
    const int wm   = wid >> 1;           // 0..3 -> m offset wm*32
    const int wn   = wid & 1;            // 0..1 -> n offset wn*64
    const int m0   = blockIdx.x * 128;
    const int n0   = blockIdx.y * 128;
    const int z    = blockIdx.z;

    const uint4* Xh = (const uint4*)(Xhi_all + (size_t)z * 4096 * 1024);
    const uint4* Xl = (const uint4*)(Xlo_all + (size_t)z * 4096 * 1024);
    const uint4* Wh = (const uint4*)(Whi_all + (size_t)z * 1024 * 1024);
    const uint4* Wl = (const uint4*)(Wlo_all + (size_t)z * 1024 * 1024);
    float* Out = (z == 0) ? Qh : ((z == 1) ? Kh : Vh);

    float acc[2][8][4];
#pragma unroll
    for (int i = 0; i < 2; i++)
#pragma unroll
        for (int j = 0; j < 8; j++)
#pragma unroll
            for (int e = 0; e < 4; e++) acc[i][j][e] = 0.f;

    // Per-lane ldmatrix address components
    const int rIn    = lane & 7;
    const int a_rsel = ((lane >> 3) & 1) * 8;   // row-block
    const int a_ksel = ((lane >> 4) & 1) * 16;  // k-byte half
    const int b_nsel = ((lane >> 4) & 1) * 8;   // n-block
    const int b_ksel = ((lane >> 3) & 1) * 16;  // k-byte half

    for (int c = 0; c < DMODEL / 64; c++) {
        const int ku4 = c * 8;
        load_tile(Xh, m0, ku4, Ah, tid);
        load_tile(Xl, m0, ku4, Al, tid);
        load_tile(Wh, n0, ku4, Bh, tid);
        load_tile(Wl, n0, ku4, Bl, tid);
        __syncthreads();

#pragma unroll
        for (int ks = 0; ks < 4; ks++) {
            uint32_t ah[2][4], al[2][4];
#pragma unroll
            for (int mi = 0; mi < 2; mi++) {
                int row = wm * 32 + mi * 16 + a_rsel + rIn;
                uint32_t off = sw128(row * 128 + ks * 32 + a_ksel);
                LDSM_X4(ah[mi][0], ah[mi][1], ah[mi][2], ah[mi][3], ah_u + off);
                LDSM_X4(al[mi][0], al[mi][1], al[mi][2], al[mi][3], al_u + off);
            }
#pragma unroll
            for (int njp = 0; njp < 4; njp++) {
                int nrow = wn * 64 + njp * 16 + b_nsel + rIn;
                uint32_t off = sw128(nrow * 128 + ks * 32 + b_ksel);
                uint32_t bhf[4], blf[4];
                LDSM_X4(bhf[0], bhf[1], bhf[2], bhf[3], bh_u + off);
                LDSM_X4(blf[0], blf[1], blf[2], blf[3], bl_u + off);
#pragma unroll
                for (int mi = 0; mi < 2; mi++) {
                    MMA_BF16(acc[mi][njp * 2],     ah[mi], bhf[0], bhf[1]);
                    MMA_BF16(acc[mi][njp * 2],     al[mi], bhf[0], bhf[1]);
                    MMA_BF16(acc[mi][njp * 2],     ah[mi], blf[0], blf[1]);
                    MMA_BF16(acc[mi][njp * 2 + 1], ah[mi], bhf[2], bhf[3]);
                    MMA_BF16(acc[mi][njp * 2 + 1], al[mi], bhf[2], bhf[3]);
                    MMA_BF16(acc[mi][njp * 2 + 1], ah[mi], blf[2], blf[3]);
                }
            }
        }
        __syncthreads();
    }

    // Epilogue: fragment -> head-split fp32 [b][h][s][hd]
    const int rr = lane >> 2;
    const int cc = (lane & 3) * 2;
#pragma unroll
    for (int mi = 0; mi < 2; mi++) {
#pragma unroll
        for (int nj = 0; nj < 8; nj++) {
            int n  = n0 + wn * 64 + nj * 8 + cc;
            int h  = n >> 6, hd = n & 63;
            int m  = m0 + wm * 32 + mi * 16 + rr;
            int bb = m >> 11, ss = m & 2047;
            float* d0 = Out + (((size_t)(bb * NHEADS + h)) * SEQ + ss) * HDIM + hd;
            *reinterpret_cast<float2*>(d0) =
                make_float2(acc[mi][nj][0], acc[mi][nj][1]);
            float* d1 = d0 + 8 * HDIM;   // m + 8
            *reinterpret_cast<float2*>(d1) =
                make_float2(acc[mi][nj][2], acc[mi][nj][3]);
        }
    }
}

// ===========================================================================
// Flash attention, fp32 FFMA (unchanged - proven correct, next target)
// ===========================================================================
#define ATTN_SMEM_FLOATS (4 * 4096 + 64 * 3 + 64 * 4)
#define ATTN_SMEM_BYTES  (ATTN_SMEM_FLOATS * 4)

__global__ __launch_bounds__(256, 2)
void attn_kernel(const float* __restrict__ Q, const float* __restrict__ K,
                 const float* __restrict__ V, float* __restrict__ Out)
{
    extern __shared__ float sm[];
    float* Qs   = sm;              // [hd][r]
    float* Ks   = sm + 4096;       // [hd][c]
    float* Vs   = sm + 8192;       // [k][hd]
    float* Ss   = sm + 12288;      // [r][k] -> P in place
    float* mrow = sm + 16384;
    float* lrow = mrow + 64;
    float* arow = lrow + 64;
    float* pred = arow + 64;       // [64][4]

    const int tid = threadIdx.x;
    const int ty = tid >> 4;
    const int tx = tid & 15;
    const int q0 = blockIdx.x * 64;
    const int h  = blockIdx.y;
    const int b  = blockIdx.z;
    const size_t base = (size_t)(b * NHEADS + h) * SEQ * HDIM;

#pragma unroll
    for (int q = 0; q < 4; q++) {
        int lin = tid + q * 256;
        int r  = lin >> 4;
        int hd = (lin & 15) * 4;
        float4 v = *reinterpret_cast<const float4*>(
            &Q[base + (size_t)(q0 + r) * HDIM + hd]);
        Qs[(hd + 0) * 64 + r] = v.x; Qs[(hd + 1) * 64 + r] = v.y;
        Qs[(hd + 2) * 64 + r] = v.z; Qs[(hd + 3) * 64 + r] = v.w;
    }
    if (tid < 64) { mrow[tid] = NEG_INF; lrow[tid] = 0.f; }

    float o[4][4];
#pragma unroll
    for (int i = 0; i < 4; i++)
#pragma unroll
        for (int j = 0; j < 4; j++) o[i][j] = 0.f;

    for (int kt = 0; kt < SEQ; kt += 64) {
        __syncthreads();

#pragma unroll
        for (int q = 0; q < 4; q++) {
            int lin = tid + q * 256;
            int c  = lin >> 4;
            int hd = (lin & 15) * 4;
            float4 v = *reinterpret_cast<const float4*>(
                &K[base + (size_t)(kt + c) * HDIM + hd]);
            Ks[(hd + 0) * 64 + c] = v.x; Ks[(hd + 1) * 64 + c] = v.y;
            Ks[(hd + 2) * 64 + c] = v.z; Ks[(hd + 3) * 64 + c] = v.w;
        }
#pragma unroll
        for (int q = 0; q < 4; q++) {
            int lin = tid + q * 256;
            int kr = lin >> 4;
            int hd = (lin & 15) * 4;
            *reinterpret_cast<float4*>(&Vs[kr * 64 + hd]) =
                *reinterpret_cast<const float4*>(
                    &V[base + (size_t)(kt + kr) * HDIM + hd]);
        }
        __syncthreads();

        float s[4][4];
#pragma unroll
        for (int i = 0; i < 4; i++)
#pragma unroll
            for (int j = 0; j < 4; j++) s[i][j] = 0.f;
#pragma unroll
        for (int kk = 0; kk < 64; kk++) {
            float a[4], bb[4];
            *reinterpret_cast<float4*>(a) =
                *reinterpret_cast<const float4*>(&Qs[kk * 64 + ty * 4]);
            *reinterpret_cast<float4*>(bb) =
                *reinterpret_cast<const float4*>(&Ks[kk * 64 + tx * 4]);
#pragma unroll
            for (int i = 0; i < 4; i++)
#pragma unroll
                for (int j = 0; j < 4; j++)
                    s[i][j] += a[i] * bb[j];
        }
#pragma unroll
        for (int i = 0; i < 4; i++) {
            float4 st = make_float4(s[i][0] * 64.f, s[i][1] * 64.f,
                                    s[i][2] * 64.f, s[i][3] * 64.f);
            *reinterpret_cast<float4*>(&Ss[(ty * 4 + i) * 64 + tx * 4]) = st;
        }
        __syncthreads();

        {
            int r = tid >> 2, c = tid & 3;
            const float* row = &Ss[r * 64 + c * 16];
            float pm = NEG_INF;
#pragma unroll
            for (int e = 0; e < 16; e++) pm = fmaxf(pm, row[e]);
            pred[r * 4 + c] = pm;
        }
        __syncthreads();
        if (tid < 64) {
            int r = tid;
            float rm = fmaxf(fmaxf(pred[r * 4 + 0], pred[r * 4 + 1]),
                             fmaxf(pred[r * 4 + 2], pred[r * 4 + 3]));
            float mold = mrow[r];
            float mnew = fmaxf(mold, rm);
            float alpha = __expf(mold - mnew);
            mrow[r] = mnew;
            arow[r] = alpha;
            lrow[r] *= alpha;
        }
        __syncthreads();

        {
            int r = tid >> 2, c = tid & 3;
            float mn = mrow[r];
            float* row = &Ss[r * 64 + c * 16];
            float ps = 0.f;
#pragma unroll
            for (int e = 0; e < 16; e++) {
                float p = __expf(row[e] - mn);
                row[e] = p;
                ps += p;
            }
            pred[r * 4 + c] = ps;
        }
        __syncthreads();
        if (tid < 64) {
            int r = tid;
            lrow[r] += pred[r * 4 + 0] + pred[r * 4 + 1] +
                       pred[r * 4 + 2] + pred[r * 4 + 3];
        }

        float al[4];
#pragma unroll
        for (int i = 0; i < 4; i++) al[i] = arow[ty * 4 + i];
#pragma unroll
        for (int i = 0; i < 4; i++)
#pragma unroll
            for (int j = 0; j < 4; j++) o[i][j] *= al[i];

#pragma unroll
        for (int kk = 0; kk < 64; kk++) {
            float p[4], vv[4];
#pragma unroll
            for (int i = 0; i < 4; i++)
                p[i] = Ss[(ty * 4 + i) * 64 + kk];
            *reinterpret_cast<float4*>(vv) =
                *reinterpret_cast<const float4*>(&Vs[kk * 64 + tx * 4]);
#pragma unroll
            for (int i = 0; i < 4; i++)
#pragma unroll
                for (int j = 0; j < 4; j++)
                    o[i][j] += p[i] * vv[j];
        }
    }
    __syncthreads();

#pragma unroll
    for (int i = 0; i < 4; i++) {
        int sidx = q0 + ty * 4 + i;
        float linv = 1.f / lrow[ty * 4 + i];
        float4 ov = make_float4(o[i][0] * linv, o[i][1] * linv,
                                o[i][2] * linv, o[i][3] * linv);
        *reinterpret_cast<float4*>(
            &Out[((size_t)(b * SEQ + sidx) * NHEADS + h) * HDIM + tx * 4]) = ov;
    }
}

// ---------------------------------------------------------------------------
extern "C" void kernel_launch(void* const* d_in, const int* in_sizes, int n_in,
                              void* d_out, int out_size)
{
    const float* q  = (const float*)d_in[0];
    const float* k  = (const float*)d_in[1];
    const float* v  = (const float*)d_in[2];
    const float* Wq = (const float*)d_in[3];
    const float* Wk = (const float*)d_in[4];
    const float* Wv = (const float*)d_in[5];
    float* out = (float*)d_out;

    float *Qh, *Kh, *Vh;
    __nv_bfloat16 *Xhi, *Xlo, *Whi, *Wlo;
    cudaGetSymbolAddress((void**)&Qh, g_Qh);
    cudaGetSymbolAddress((void**)&Kh, g_Kh);
    cudaGetSymbolAddress((void**)&Vh, g_Vh);
    cudaGetSymbolAddress((void**)&Xhi, g_Xhi);
    cudaGetSymbolAddress((void**)&Xlo, g_Xlo);
    cudaGetSymbolAddress((void**)&Whi, g_Whi);
    cudaGetSymbolAddress((void**)&Wlo, g_Wlo);

    cudaFuncSetAttribute(proj_mma_kernel,
                         cudaFuncAttributeMaxDynamicSharedMemorySize, PROJ_SMEM);
    cudaFuncSetAttribute(attn_kernel,
                         cudaFuncAttributeMaxDynamicSharedMemorySize,
                         ATTN_SMEM_BYTES);

    const int nX4 = 4096 * 1024 / 4;
    const int nW4 = 1024 * 1024 / 4;
    split_kernel<<<nX4 / 256, 256>>>((const float4*)q, Xhi,               Xlo,               nX4);
    split_kernel<<<nX4 / 256, 256>>>((const float4*)k, Xhi + 4194304,     Xlo + 4194304,     nX4);
    split_kernel<<<nX4 / 256, 256>>>((const float4*)v, Xhi + 2 * 4194304, Xlo + 2 * 4194304, nX4);
    split_kernel<<<nW4 / 256, 256>>>((const float4*)Wq, Whi,               Wlo,               nW4);
    split_kernel<<<nW4 / 256, 256>>>((const float4*)Wk, Whi + 1048576,     Wlo + 1048576,     nW4);
    split_kernel<<<nW4 / 256, 256>>>((const float4*)Wv, Whi + 2 * 1048576, Wlo + 2 * 1048576, nW4);

    dim3 pg(4096 / 128, 1024 / 128, 3);
    proj_mma_kernel<<<pg, 256, PROJ_SMEM>>>(Xhi, Xlo, Whi, Wlo, Qh, Kh, Vh);

    dim3 ag(SEQ / 64, NHEADS, BATCH);
    attn_kernel<<<ag, 256, ATTN_SMEM_BYTES>>>(Qh, Kh, Vh, out);
}

// round 4
// speedup vs baseline: 3.1794x; 2.5087x over previous
#include <cuda_runtime.h>
#include <cuda_bf16.h>
#include <cstdint>

// ---------------------------------------------------------------------------
// MultiHeadAttention: out = softmax((XQ Wq^T)(XK Wk^T)^T * 64) (XV Wv^T)
// b=2, s=2048, d=1024, heads=16, hd=64.
// Round 4: attention on mma.sync too. Projections emit bf16 hi/lo directly;
// flash attention with 3-term split QK^T and PV, register softmax,
// cp.async double-buffered K/V tiles.
// ---------------------------------------------------------------------------

#define BATCH     2
#define SEQ       2048
#define DMODEL    1024
#define NHEADS    16
#define HDIM      64

// bf16x2 split of raw inputs/weights (for projection GEMMs)
__device__ __nv_bfloat16 g_Xhi[3ull * 4096 * 1024];
__device__ __nv_bfloat16 g_Xlo[3ull * 4096 * 1024];
__device__ __nv_bfloat16 g_Whi[3ull * 1024 * 1024];
__device__ __nv_bfloat16 g_Wlo[3ull * 1024 * 1024];
// Projected Q/K/V, head-split [b][h][s][hd], bf16 hi/lo pairs
__device__ __nv_bfloat16 g_Qhi[BATCH * NHEADS * SEQ * HDIM];
__device__ __nv_bfloat16 g_Qlo[BATCH * NHEADS * SEQ * HDIM];
__device__ __nv_bfloat16 g_Khi[BATCH * NHEADS * SEQ * HDIM];
__device__ __nv_bfloat16 g_Klo[BATCH * NHEADS * SEQ * HDIM];
__device__ __nv_bfloat16 g_Vhi[BATCH * NHEADS * SEQ * HDIM];
__device__ __nv_bfloat16 g_Vlo[BATCH * NHEADS * SEQ * HDIM];

__device__ __forceinline__ uint32_t smem_u32(const void* p) {
    uint32_t a;
    asm("{ .reg .u64 t; cvta.to.shared.u64 t, %1; cvt.u32.u64 %0, t; }"
        : "=r"(a) : "l"(p));
    return a;
}
__device__ __forceinline__ uint32_t sw128(uint32_t b) {
    return b ^ ((b >> 3) & 0x70);
}

#define LDSM_X4(r0, r1, r2, r3, addr) \
    asm volatile("ldmatrix.sync.aligned.m8n8.x4.shared.b16 {%0,%1,%2,%3}, [%4];" \
                 : "=r"(r0), "=r"(r1), "=r"(r2), "=r"(r3) : "r"(addr))
#define LDSM_X4_T(r0, r1, r2, r3, addr) \
    asm volatile("ldmatrix.sync.aligned.m8n8.x4.trans.shared.b16 {%0,%1,%2,%3}, [%4];" \
                 : "=r"(r0), "=r"(r1), "=r"(r2), "=r"(r3) : "r"(addr))

#define MMA_BF16(d, a, b0, b1) \
    asm volatile("mma.sync.aligned.m16n8k16.row.col.f32.bf16.bf16.f32 " \
                 "{%0,%1,%2,%3}, {%4,%5,%6,%7}, {%8,%9}, {%0,%1,%2,%3};" \
                 : "+f"((d)[0]), "+f"((d)[1]), "+f"((d)[2]), "+f"((d)[3]) \
                 : "r"((a)[0]), "r"((a)[1]), "r"((a)[2]), "r"((a)[3]), \
                   "r"(b0), "r"(b1))

#define CP_A16(dst, src) \
    asm volatile("cp.async.cg.shared.global [%0], [%1], 16;" \
                 :: "r"(dst), "l"(src) : "memory")
#define CP_COMMIT() asm volatile("cp.async.commit_group;" ::: "memory")
#define CP_WAIT(n)  asm volatile("cp.async.wait_group %0;" :: "n"(n) : "memory")

__device__ __forceinline__ uint32_t pack_bf16(float lo, float hi) {
    uint32_t u = (uint32_t)__bfloat16_as_ushort(__float2bfloat16(lo)) |
                 ((uint32_t)__bfloat16_as_ushort(__float2bfloat16(hi)) << 16);
    return u;
}

// ===========================================================================
// Split kernel: x -> (bf16 hi, bf16 lo)
// ===========================================================================
__global__ void split_kernel(const float4* __restrict__ src,
                             __nv_bfloat16* __restrict__ hi,
                             __nv_bfloat16* __restrict__ lo, int n4)
{
    int i = blockIdx.x * 256 + threadIdx.x;
    if (i >= n4) return;
    float4 v = src[i];
    float xs[4] = {v.x, v.y, v.z, v.w};
    uint32_t hb[4], lb[4];
#pragma unroll
    for (int j = 0; j < 4; j++) {
        __nv_bfloat16 h = __float2bfloat16(xs[j]);
        __nv_bfloat16 l = __float2bfloat16(xs[j] - __bfloat162float(h));
        hb[j] = (uint32_t)__bfloat16_as_ushort(h);
        lb[j] = (uint32_t)__bfloat16_as_ushort(l);
    }
    uint2 hp, lp;
    hp.x = hb[0] | (hb[1] << 16); hp.y = hb[2] | (hb[3] << 16);
    lp.x = lb[0] | (lb[1] << 16); lp.y = lb[2] | (lb[3] << 16);
    reinterpret_cast<uint2*>(hi)[i] = hp;
    reinterpret_cast<uint2*>(lo)[i] = lp;
}

// ===========================================================================
// Projection GEMM via mma.sync (validated in R3). Epilogue now emits
// bf16 hi/lo pairs in head-split layout [b][h][s][hd].
// ===========================================================================
#define PROJ_SMEM (4 * 16384)

__device__ __forceinline__ void load_tile(const uint4* __restrict__ g,
                                          int row0, int ku4, char* smt, int tid)
{
#pragma unroll
    for (int q = 0; q < 4; q++) {
        int lin = tid + q * 256;
        int row = lin >> 3, col = lin & 7;
        uint4 v = g[(size_t)(row0 + row) * 128 + ku4 + col];
        *reinterpret_cast<uint4*>(smt + sw128(row * 128 + col * 16)) = v;
    }
}

__global__ __launch_bounds__(256, 2)
void proj_mma_kernel(const __nv_bfloat16* __restrict__ Xhi_all,
                     const __nv_bfloat16* __restrict__ Xlo_all,
                     const __nv_bfloat16* __restrict__ Whi_all,
                     const __nv_bfloat16* __restrict__ Wlo_all,
                     __nv_bfloat16* __restrict__ Qhi, __nv_bfloat16* __restrict__ Qlo,
                     __nv_bfloat16* __restrict__ Khi, __nv_bfloat16* __restrict__ Klo,
                     __nv_bfloat16* __restrict__ Vhi, __nv_bfloat16* __restrict__ Vlo)
{
    extern __shared__ char smp[];
    char* Ah = smp;
    char* Al = smp + 16384;
    char* Bh = smp + 32768;
    char* Bl = smp + 49152;
    const uint32_t ah_u = smem_u32(Ah), al_u = smem_u32(Al);
    const uint32_t bh_u = smem_u32(Bh), bl_u = smem_u32(Bl);

    const int tid  = threadIdx.x;
    const int wid  = tid >> 5, lane = tid & 31;
    const int wm   = wid >> 1;
    const int wn   = wid & 1;
    const int m0   = blockIdx.x * 128;
    const int n0   = blockIdx.y * 128;
    const int z    = blockIdx.z;

    const uint4* Xh = (const uint4*)(Xhi_all + (size_t)z * 4096 * 1024);
    const uint4* Xl = (const uint4*)(Xlo_all + (size_t)z * 4096 * 1024);
    const uint4* Wh = (const uint4*)(Whi_all + (size_t)z * 1024 * 1024);
    const uint4* Wl = (const uint4*)(Wlo_all + (size_t)z * 1024 * 1024);
    __nv_bfloat16* OutHi = (z == 0) ? Qhi : ((z == 1) ? Khi : Vhi);
    __nv_bfloat16* OutLo = (z == 0) ? Qlo : ((z == 1) ? Klo : Vlo);

    float acc[2][8][4];
#pragma unroll
    for (int i = 0; i < 2; i++)
#pragma unroll
        for (int j = 0; j < 8; j++)
#pragma unroll
            for (int e = 0; e < 4; e++) acc[i][j][e] = 0.f;

    const int rIn    = lane & 7;
    const int a_rsel = ((lane >> 3) & 1) * 8;
    const int a_ksel = ((lane >> 4) & 1) * 16;
    const int b_nsel = ((lane >> 4) & 1) * 8;
    const int b_ksel = ((lane >> 3) & 1) * 16;

    for (int c = 0; c < DMODEL / 64; c++) {
        const int ku4 = c * 8;
        load_tile(Xh, m0, ku4, Ah, tid);
        load_tile(Xl, m0, ku4, Al, tid);
        load_tile(Wh, n0, ku4, Bh, tid);
        load_tile(Wl, n0, ku4, Bl, tid);
        __syncthreads();

#pragma unroll
        for (int ks = 0; ks < 4; ks++) {
            uint32_t ah[2][4], al[2][4];
#pragma unroll
            for (int mi = 0; mi < 2; mi++) {
                int row = wm * 32 + mi * 16 + a_rsel + rIn;
                uint32_t off = sw128(row * 128 + ks * 32 + a_ksel);
                LDSM_X4(ah[mi][0], ah[mi][1], ah[mi][2], ah[mi][3], ah_u + off);
                LDSM_X4(al[mi][0], al[mi][1], al[mi][2], al[mi][3], al_u + off);
            }
#pragma unroll
            for (int njp = 0; njp < 4; njp++) {
                int nrow = wn * 64 + njp * 16 + b_nsel + rIn;
                uint32_t off = sw128(nrow * 128 + ks * 32 + b_ksel);
                uint32_t bhf[4], blf[4];
                LDSM_X4(bhf[0], bhf[1], bhf[2], bhf[3], bh_u + off);
                LDSM_X4(blf[0], blf[1], blf[2], blf[3], bl_u + off);
#pragma unroll
                for (int mi = 0; mi < 2; mi++) {
                    MMA_BF16(acc[mi][njp * 2],     ah[mi], bhf[0], bhf[1]);
                    MMA_BF16(acc[mi][njp * 2],     al[mi], bhf[0], bhf[1]);
                    MMA_BF16(acc[mi][njp * 2],     ah[mi], blf[0], blf[1]);
                    MMA_BF16(acc[mi][njp * 2 + 1], ah[mi], bhf[2], bhf[3]);
                    MMA_BF16(acc[mi][njp * 2 + 1], al[mi], bhf[2], bhf[3]);
                    MMA_BF16(acc[mi][njp * 2 + 1], ah[mi], blf[2], blf[3]);
                }
            }
        }
        __syncthreads();
    }

    // Epilogue: fp32 acc -> bf16 hi/lo pairs, head-split [b][h][s][hd]
    const int rr = lane >> 2;
    const int cc = (lane & 3) * 2;
#pragma unroll
    for (int mi = 0; mi < 2; mi++) {
#pragma unroll
        for (int nj = 0; nj < 8; nj++) {
            int n  = n0 + wn * 64 + nj * 8 + cc;
            int h  = n >> 6, hd = n & 63;
            int m  = m0 + wm * 32 + mi * 16 + rr;
            int bb = m >> 11, ss = m & 2047;
            size_t idx0 = (((size_t)(bb * NHEADS + h)) * SEQ + ss) * HDIM + hd;
#pragma unroll
            for (int half = 0; half < 2; half++) {   // rows m, m+8
                float v0 = acc[mi][nj][half * 2 + 0];
                float v1 = acc[mi][nj][half * 2 + 1];
                __nv_bfloat16 h0 = __float2bfloat16(v0);
                __nv_bfloat16 h1 = __float2bfloat16(v1);
                uint32_t uhi = (uint32_t)__bfloat16_as_ushort(h0) |
                               ((uint32_t)__bfloat16_as_ushort(h1) << 16);
                uint32_t ulo = pack_bf16(v0 - __bfloat162float(h0),
                                         v1 - __bfloat162float(h1));
                size_t idx = idx0 + (size_t)half * 8 * HDIM;
                *reinterpret_cast<uint32_t*>(OutHi + idx) = uhi;
                *reinterpret_cast<uint32_t*>(OutLo + idx) = ulo;
            }
        }
    }
}

// ===========================================================================
// Tensor-core flash attention.
// CTA: 128 q-rows x (head, batch). 8 warps x 16 q-rows. Key tiles of 64.
// SMEM: Qhi[16K] Qlo[16K] | 2 x {Khi,Klo,Vhi,Vlo}[8K each] = 96 KB.
// ===========================================================================
#define AT_SMEM (32768 + 2 * 32768)

__global__ __launch_bounds__(256)
void attn_tc_kernel(const __nv_bfloat16* __restrict__ Qhi,
                    const __nv_bfloat16* __restrict__ Qlo,
                    const __nv_bfloat16* __restrict__ Khi,
                    const __nv_bfloat16* __restrict__ Klo,
                    const __nv_bfloat16* __restrict__ Vhi,
                    const __nv_bfloat16* __restrict__ Vlo,
                    float* __restrict__ Out)
{
    extern __shared__ char sma[];
    const uint32_t sm0 = smem_u32(sma);
    const int tid  = threadIdx.x;
    const int lane = tid & 31;
    const int wq   = tid >> 5;           // warp -> q-rows wq*16..+15
    const int q0   = blockIdx.x * 128;
    const int h    = blockIdx.y;
    const int b    = blockIdx.z;
    const size_t base = ((size_t)(b * NHEADS + h)) * SEQ * HDIM;

    const uint4* gqh = (const uint4*)(Qhi + base + (size_t)q0 * HDIM);
    const uint4* gql = (const uint4*)(Qlo + base + (size_t)q0 * HDIM);
    const uint4* gkh = (const uint4*)(Khi + base);
    const uint4* gkl = (const uint4*)(Klo + base);
    const uint4* gvh = (const uint4*)(Vhi + base);
    const uint4* gvl = (const uint4*)(Vlo + base);

    // ---- load Q tile (128 x 64 bf16, hi+lo) into smem
#pragma unroll
    for (int i = 0; i < 4; i++) {
        int lin = tid + i * 256;
        int row = lin >> 3, col = lin & 7;
        uint32_t off = sw128(row * 128 + col * 16);
        *reinterpret_cast<uint4*>(sma + off)         = gqh[row * 8 + col];
        *reinterpret_cast<uint4*>(sma + 16384 + off) = gql[row * 8 + col];
    }

    // ---- preload K/V tile 0 (cp.async)
    auto kv_fill = [&](uint32_t dstbase, int kt) {
#pragma unroll
        for (int i = 0; i < 8; i++) {
            int lin = tid + i * 256;
            int mat = lin >> 9;
            int rem = lin & 511;
            int row = rem >> 3, col = rem & 7;
            const uint4* src =
                (mat == 0 ? gkh : mat == 1 ? gkl : mat == 2 ? gvh : gvl)
                + (size_t)(kt + row) * 8 + col;
            uint32_t dst = dstbase + mat * 8192 + sw128(row * 128 + col * 16);
            CP_A16(dst, src);
        }
    };
    kv_fill(sm0 + 32768, 0);
    CP_COMMIT();

    __syncthreads();   // Q smem ready

    // ---- Q fragments (kept in registers for the whole kernel)
    const int rIn    = lane & 7;
    const int a_rsel = ((lane >> 3) & 1) * 8;
    const int a_ksel = ((lane >> 4) & 1) * 16;
    const int b_nsel = ((lane >> 4) & 1) * 8;
    const int b_ksel = ((lane >> 3) & 1) * 16;
    const int v_rsel = ((lane >> 3) & 1) * 8;
    const int v_nsel = ((lane >> 4) & 1) * 16;

    uint32_t qh[4][4], ql[4][4];
#pragma unroll
    for (int ks = 0; ks < 4; ks++) {
        uint32_t off = sw128((wq * 16 + a_rsel + rIn) * 128 + ks * 32 + a_ksel);
        LDSM_X4(qh[ks][0], qh[ks][1], qh[ks][2], qh[ks][3], sm0 + off);
        LDSM_X4(ql[ks][0], ql[ks][1], ql[ks][2], ql[ks][3], sm0 + 16384 + off);
    }

    float o[8][4];
#pragma unroll
    for (int v = 0; v < 8; v++)
#pragma unroll
        for (int e = 0; e < 4; e++) o[v][e] = 0.f;
    float m0r = -3.0e38f, m1r = -3.0e38f;
    float l0 = 0.f, l1 = 0.f;

    for (int t = 0; t < SEQ / 64; t++) {
        if (t + 1 < SEQ / 64) {
            kv_fill(sm0 + 32768 + ((t + 1) & 1) * 32768, (t + 1) * 64);
            CP_COMMIT();
            CP_WAIT(1);
        } else {
            CP_WAIT(0);
        }
        __syncthreads();
        const uint32_t kb = sm0 + 32768 + (t & 1) * 32768;
        const uint32_t vb = kb + 16384;

        // ---- S = Q K^T (3-term split), unscaled
        float s[8][4];
#pragma unroll
        for (int j = 0; j < 8; j++)
#pragma unroll
            for (int e = 0; e < 4; e++) s[j][e] = 0.f;
#pragma unroll
        for (int ks = 0; ks < 4; ks++) {
#pragma unroll
            for (int np = 0; np < 4; np++) {
                uint32_t off = sw128((np * 16 + b_nsel + rIn) * 128 + ks * 32 + b_ksel);
                uint32_t kf[4], lf[4];
                LDSM_X4(kf[0], kf[1], kf[2], kf[3], kb + off);
                LDSM_X4(lf[0], lf[1], lf[2], lf[3], kb + 8192 + off);
                MMA_BF16(s[np * 2],     qh[ks], kf[0], kf[1]);
                MMA_BF16(s[np * 2],     ql[ks], kf[0], kf[1]);
                MMA_BF16(s[np * 2],     qh[ks], lf[0], lf[1]);
                MMA_BF16(s[np * 2 + 1], qh[ks], kf[2], kf[3]);
                MMA_BF16(s[np * 2 + 1], ql[ks], kf[2], kf[3]);
                MMA_BF16(s[np * 2 + 1], qh[ks], lf[2], lf[3]);
            }
        }

        // ---- register softmax (rows r=lane>>2 and r+8), scaled domain x64
        float mt0 = -3.0e38f, mt1 = -3.0e38f;
#pragma unroll
        for (int j = 0; j < 8; j++) {
            mt0 = fmaxf(mt0, fmaxf(s[j][0], s[j][1]));
            mt1 = fmaxf(mt1, fmaxf(s[j][2], s[j][3]));
        }
        mt0 = fmaxf(mt0, __shfl_xor_sync(0xffffffffu, mt0, 1));
        mt0 = fmaxf(mt0, __shfl_xor_sync(0xffffffffu, mt0, 2));
        mt1 = fmaxf(mt1, __shfl_xor_sync(0xffffffffu, mt1, 1));
        mt1 = fmaxf(mt1, __shfl_xor_sync(0xffffffffu, mt1, 2));
        float M0 = fmaxf(m0r, mt0 * 64.f);
        float M1 = fmaxf(m1r, mt1 * 64.f);
        float a0 = __expf(m0r - M0);
        float a1 = __expf(m1r - M1);
        m0r = M0; m1r = M1;

        float rs0 = 0.f, rs1 = 0.f;
        uint32_t aphi[4][4], aplo[4][4];
#pragma unroll
        for (int jp = 0; jp < 4; jp++) {
#pragma unroll
            for (int half = 0; half < 2; half++) {   // frags 2jp, 2jp+1
                int j = jp * 2 + half;
                float p0 = __expf(fmaf(s[j][0], 64.f, -M0));
                float p1 = __expf(fmaf(s[j][1], 64.f, -M0));
                float p2 = __expf(fmaf(s[j][2], 64.f, -M1));
                float p3 = __expf(fmaf(s[j][3], 64.f, -M1));
                rs0 += p0 + p1;
                rs1 += p2 + p3;
                __nv_bfloat16 h0 = __float2bfloat16(p0);
                __nv_bfloat16 h1 = __float2bfloat16(p1);
                __nv_bfloat16 h2 = __float2bfloat16(p2);
                __nv_bfloat16 h3 = __float2bfloat16(p3);
                aphi[jp][half * 2 + 0] =
                    (uint32_t)__bfloat16_as_ushort(h0) |
                    ((uint32_t)__bfloat16_as_ushort(h1) << 16);
                aphi[jp][half * 2 + 1] =
                    (uint32_t)__bfloat16_as_ushort(h2) |
                    ((uint32_t)__bfloat16_as_ushort(h3) << 16);
                aplo[jp][half * 2 + 0] =
                    pack_bf16(p0 - __bfloat162float(h0), p1 - __bfloat162float(h1));
                aplo[jp][half * 2 + 1] =
                    pack_bf16(p2 - __bfloat162float(h2), p3 - __bfloat162float(h3));
            }
        }
        // NOTE: A-frag order is {a0,a1,a2,a3} = {f2jp.c01, f2jp.c23, f2jp+1.c01, f2jp+1.c23}
        // half=0 wrote slots 0,1 (c01->a0, c23->a1); half=1 wrote slots 2,3. Correct.

        rs0 += __shfl_xor_sync(0xffffffffu, rs0, 1);
        rs0 += __shfl_xor_sync(0xffffffffu, rs0, 2);
        rs1 += __shfl_xor_sync(0xffffffffu, rs1, 1);
        rs1 += __shfl_xor_sync(0xffffffffu, rs1, 2);
        l0 = l0 * a0 + rs0;
        l1 = l1 * a1 + rs1;
#pragma unroll
        for (int v = 0; v < 8; v++) {
            o[v][0] *= a0; o[v][1] *= a0;
            o[v][2] *= a1; o[v][3] *= a1;
        }

        // ---- O += P V (3-term split), V via ldmatrix.trans
#pragma unroll
        for (int t4 = 0; t4 < 4; t4++) {
#pragma unroll
            for (int vp = 0; vp < 4; vp++) {
                uint32_t off = sw128((t4 * 16 + v_rsel + rIn) * 128 + vp * 32 + v_nsel);
                uint32_t vh[4], vl[4];
                LDSM_X4_T(vh[0], vh[1], vh[2], vh[3], vb + off);
                LDSM_X4_T(vl[0], vl[1], vl[2], vl[3], vb + 8192 + off);
                MMA_BF16(o[vp * 2],     aphi[t4], vh[0], vh[1]);
                MMA_BF16(o[vp * 2],     aplo[t4], vh[0], vh[1]);
                MMA_BF16(o[vp * 2],     aphi[t4], vl[0], vl[1]);
                MMA_BF16(o[vp * 2 + 1], aphi[t4], vh[2], vh[3]);
                MMA_BF16(o[vp * 2 + 1], aplo[t4], vh[2], vh[3]);
                MMA_BF16(o[vp * 2 + 1], aphi[t4], vl[2], vl[3]);
            }
        }
        __syncthreads();   // all reads of this buffer done before refill
    }

    // ---- epilogue: normalize, write out[b][s][h*64+hd]
    float inv0 = 1.f / l0;
    float inv1 = 1.f / l1;
    int s0 = q0 + wq * 16 + (lane >> 2);
    int hd0 = h * 64 + 2 * (lane & 3);
#pragma unroll
    for (int v = 0; v < 8; v++) {
        float2 w0 = make_float2(o[v][0] * inv0, o[v][1] * inv0);
        float2 w1 = make_float2(o[v][2] * inv1, o[v][3] * inv1);
        *reinterpret_cast<float2*>(
            &Out[(size_t)(b * SEQ + s0) * DMODEL + hd0 + v * 8]) = w0;
        *reinterpret_cast<float2*>(
            &Out[(size_t)(b * SEQ + s0 + 8) * DMODEL + hd0 + v * 8]) = w1;
    }
}

// ---------------------------------------------------------------------------
extern "C" void kernel_launch(void* const* d_in, const int* in_sizes, int n_in,
                              void* d_out, int out_size)
{
    const float* q  = (const float*)d_in[0];
    const float* k  = (const float*)d_in[1];
    const float* v  = (const float*)d_in[2];
    const float* Wq = (const float*)d_in[3];
    const float* Wk = (const float*)d_in[4];
    const float* Wv = (const float*)d_in[5];
    float* out = (float*)d_out;

    __nv_bfloat16 *Xhi, *Xlo, *Whi, *Wlo;
    __nv_bfloat16 *Qhi, *Qlo, *Khi, *Klo, *Vhi, *Vlo;
    cudaGetSymbolAddress((void**)&Xhi, g_Xhi);
    cudaGetSymbolAddress((void**)&Xlo, g_Xlo);
    cudaGetSymbolAddress((void**)&Whi, g_Whi);
    cudaGetSymbolAddress((void**)&Wlo, g_Wlo);
    cudaGetSymbolAddress((void**)&Qhi, g_Qhi);
    cudaGetSymbolAddress((void**)&Qlo, g_Qlo);
    cudaGetSymbolAddress((void**)&Khi, g_Khi);
    cudaGetSymbolAddress((void**)&Klo, g_Klo);
    cudaGetSymbolAddress((void**)&Vhi, g_Vhi);
    cudaGetSymbolAddress((void**)&Vlo, g_Vlo);

    cudaFuncSetAttribute(proj_mma_kernel,
                         cudaFuncAttributeMaxDynamicSharedMemorySize, PROJ_SMEM);
    cudaFuncSetAttribute(attn_tc_kernel,
                         cudaFuncAttributeMaxDynamicSharedMemorySize, AT_SMEM);

    const int nX4 = 4096 * 1024 / 4;
    const int nW4 = 1024 * 1024 / 4;
    split_kernel<<<nX4 / 256, 256>>>((const float4*)q, Xhi,               Xlo,               nX4);
    split_kernel<<<nX4 / 256, 256>>>((const float4*)k, Xhi + 4194304,     Xlo + 4194304,     nX4);
    split_kernel<<<nX4 / 256, 256>>>((const float4*)v, Xhi + 2 * 4194304, Xlo + 2 * 4194304, nX4);
    split_kernel<<<nW4 / 256, 256>>>((const float4*)Wq, Whi,               Wlo,               nW4);
    split_kernel<<<nW4 / 256, 256>>>((const float4*)Wk, Whi + 1048576,     Wlo + 1048576,     nW4);
    split_kernel<<<nW4 / 256, 256>>>((const float4*)Wv, Whi + 2 * 1048576, Wlo + 2 * 1048576, nW4);

    dim3 pg(4096 / 128, 1024 / 128, 3);
    proj_mma_kernel<<<pg, 256, PROJ_SMEM>>>(Xhi, Xlo, Whi, Wlo,
                                            Qhi, Qlo, Khi, Klo, Vhi, Vlo);

    dim3 ag(SEQ / 128, NHEADS, BATCH);   // (16, 16, 2)
    attn_tc_kernel<<<ag, 256, AT_SMEM>>>(Qhi, Qlo, Khi, Klo, Vhi, Vlo, out);
}

// round 5
// speedup vs baseline: 3.3573x; 1.0560x over previous
#include <cuda_runtime.h>
#include <cuda_bf16.h>
#include <cstdint>

// ---------------------------------------------------------------------------
// MultiHeadAttention: out = softmax((XQ Wq^T)(XK Wk^T)^T * 64) (XV Wv^T)
// b=2, s=2048, d=1024, heads=16, hd=64.
// Round 5: (1) bf16x2 split fused into projection loads (split kernels gone),
// (2) PV uses 2 terms with l computed from rounded P (error cancellation).
// ---------------------------------------------------------------------------

#define BATCH     2
#define SEQ       2048
#define DMODEL    1024
#define NHEADS    16
#define HDIM      64

// Projected Q/K/V, head-split [b][h][s][hd], bf16 hi/lo pairs
__device__ __nv_bfloat16 g_Qhi[BATCH * NHEADS * SEQ * HDIM];
__device__ __nv_bfloat16 g_Qlo[BATCH * NHEADS * SEQ * HDIM];
__device__ __nv_bfloat16 g_Khi[BATCH * NHEADS * SEQ * HDIM];
__device__ __nv_bfloat16 g_Klo[BATCH * NHEADS * SEQ * HDIM];
__device__ __nv_bfloat16 g_Vhi[BATCH * NHEADS * SEQ * HDIM];
__device__ __nv_bfloat16 g_Vlo[BATCH * NHEADS * SEQ * HDIM];

__device__ __forceinline__ uint32_t smem_u32(const void* p) {
    uint32_t a;
    asm("{ .reg .u64 t; cvta.to.shared.u64 t, %1; cvt.u32.u64 %0, t; }"
        : "=r"(a) : "l"(p));
    return a;
}
__device__ __forceinline__ uint32_t sw128(uint32_t b) {
    return b ^ ((b >> 3) & 0x70);
}

#define LDSM_X4(r0, r1, r2, r3, addr) \
    asm volatile("ldmatrix.sync.aligned.m8n8.x4.shared.b16 {%0,%1,%2,%3}, [%4];" \
                 : "=r"(r0), "=r"(r1), "=r"(r2), "=r"(r3) : "r"(addr))
#define LDSM_X4_T(r0, r1, r2, r3, addr) \
    asm volatile("ldmatrix.sync.aligned.m8n8.x4.trans.shared.b16 {%0,%1,%2,%3}, [%4];" \
                 : "=r"(r0), "=r"(r1), "=r"(r2), "=r"(r3) : "r"(addr))

#define MMA_BF16(d, a, b0, b1) \
    asm volatile("mma.sync.aligned.m16n8k16.row.col.f32.bf16.bf16.f32 " \
                 "{%0,%1,%2,%3}, {%4,%5,%6,%7}, {%8,%9}, {%0,%1,%2,%3};" \
                 : "+f"((d)[0]), "+f"((d)[1]), "+f"((d)[2]), "+f"((d)[3]) \
                 : "r"((a)[0]), "r"((a)[1]), "r"((a)[2]), "r"((a)[3]), \
                   "r"(b0), "r"(b1))

#define CP_A16(dst, src) \
    asm volatile("cp.async.cg.shared.global [%0], [%1], 16;" \
                 :: "r"(dst), "l"(src) : "memory")
#define CP_COMMIT() asm volatile("cp.async.commit_group;" ::: "memory")
#define CP_WAIT(n)  asm volatile("cp.async.wait_group %0;" :: "n"(n) : "memory")

__device__ __forceinline__ uint32_t pack_bf16(float lo, float hi) {
    uint32_t u = (uint32_t)__bfloat16_as_ushort(__float2bfloat16(lo)) |
                 ((uint32_t)__bfloat16_as_ushort(__float2bfloat16(hi)) << 16);
    return u;
}

// ===========================================================================
// Projection GEMM via mma.sync (validated R3/R4). The bf16x2 split is fused
// into the tile load: read fp32, emit hi/lo bf16 tiles into smem.
// Out[m,n] = sum_k X[m,k]*W[n,k]; epilogue emits bf16 hi/lo head-split.
// ===========================================================================
#define PROJ_SMEM (4 * 16384)

__device__ __forceinline__ void load_split_tile(const float* __restrict__ g,
                                                int row0, int kcol0,
                                                char* smHi, char* smLo, int tid)
{
#pragma unroll
    for (int q = 0; q < 4; q++) {
        int lin = tid + q * 256;
        int row = lin >> 3, cg = lin & 7;
        const float4* src = reinterpret_cast<const float4*>(
            g + (size_t)(row0 + row) * DMODEL + kcol0 + cg * 8);
        float4 v0 = src[0], v1 = src[1];
        float xs[8] = {v0.x, v0.y, v0.z, v0.w, v1.x, v1.y, v1.z, v1.w};
        uint32_t hw[4], lw[4];
#pragma unroll
        for (int j = 0; j < 4; j++) {
            __nv_bfloat16 h0 = __float2bfloat16(xs[j * 2]);
            __nv_bfloat16 h1 = __float2bfloat16(xs[j * 2 + 1]);
            hw[j] = (uint32_t)__bfloat16_as_ushort(h0) |
                    ((uint32_t)__bfloat16_as_ushort(h1) << 16);
            lw[j] = pack_bf16(xs[j * 2] - __bfloat162float(h0),
                              xs[j * 2 + 1] - __bfloat162float(h1));
        }
        uint32_t off = sw128(row * 128 + cg * 16);
        *reinterpret_cast<uint4*>(smHi + off) = make_uint4(hw[0], hw[1], hw[2], hw[3]);
        *reinterpret_cast<uint4*>(smLo + off) = make_uint4(lw[0], lw[1], lw[2], lw[3]);
    }
}

__global__ __launch_bounds__(256, 2)
void proj_mma_kernel(const float* __restrict__ Xq, const float* __restrict__ Xk,
                     const float* __restrict__ Xv,
                     const float* __restrict__ Wq, const float* __restrict__ Wk,
                     const float* __restrict__ Wv,
                     __nv_bfloat16* __restrict__ Qhi, __nv_bfloat16* __restrict__ Qlo,
                     __nv_bfloat16* __restrict__ Khi, __nv_bfloat16* __restrict__ Klo,
                     __nv_bfloat16* __restrict__ Vhi, __nv_bfloat16* __restrict__ Vlo)
{
    extern __shared__ char smp[];
    char* Ah = smp;
    char* Al = smp + 16384;
    char* Bh = smp + 32768;
    char* Bl = smp + 49152;
    const uint32_t ah_u = smem_u32(Ah), al_u = smem_u32(Al);
    const uint32_t bh_u = smem_u32(Bh), bl_u = smem_u32(Bl);

    const int tid  = threadIdx.x;
    const int wid  = tid >> 5, lane = tid & 31;
    const int wm   = wid >> 1;
    const int wn   = wid & 1;
    const int m0   = blockIdx.x * 128;
    const int n0   = blockIdx.y * 128;
    const int z    = blockIdx.z;

    const float* X = (z == 0) ? Xq : ((z == 1) ? Xk : Xv);
    const float* W = (z == 0) ? Wq : ((z == 1) ? Wk : Wv);
    __nv_bfloat16* OutHi = (z == 0) ? Qhi : ((z == 1) ? Khi : Vhi);
    __nv_bfloat16* OutLo = (z == 0) ? Qlo : ((z == 1) ? Klo : Vlo);

    float acc[2][8][4];
#pragma unroll
    for (int i = 0; i < 2; i++)
#pragma unroll
        for (int j = 0; j < 8; j++)
#pragma unroll
            for (int e = 0; e < 4; e++) acc[i][j][e] = 0.f;

    const int rIn    = lane & 7;
    const int a_rsel = ((lane >> 3) & 1) * 8;
    const int a_ksel = ((lane >> 4) & 1) * 16;
    const int b_nsel = ((lane >> 4) & 1) * 8;
    const int b_ksel = ((lane >> 3) & 1) * 16;

    for (int c = 0; c < DMODEL / 64; c++) {
        const int k0 = c * 64;
        load_split_tile(X, m0, k0, Ah, Al, tid);
        load_split_tile(W, n0, k0, Bh, Bl, tid);
        __syncthreads();

#pragma unroll
        for (int ks = 0; ks < 4; ks++) {
            uint32_t ah[2][4], al[2][4];
#pragma unroll
            for (int mi = 0; mi < 2; mi++) {
                int row = wm * 32 + mi * 16 + a_rsel + rIn;
                uint32_t off = sw128(row * 128 + ks * 32 + a_ksel);
                LDSM_X4(ah[mi][0], ah[mi][1], ah[mi][2], ah[mi][3], ah_u + off);
                LDSM_X4(al[mi][0], al[mi][1], al[mi][2], al[mi][3], al_u + off);
            }
#pragma unroll
            for (int njp = 0; njp < 4; njp++) {
                int nrow = wn * 64 + njp * 16 + b_nsel + rIn;
                uint32_t off = sw128(nrow * 128 + ks * 32 + b_ksel);
                uint32_t bhf[4], blf[4];
                LDSM_X4(bhf[0], bhf[1], bhf[2], bhf[3], bh_u + off);
                LDSM_X4(blf[0], blf[1], blf[2], blf[3], bl_u + off);
#pragma unroll
                for (int mi = 0; mi < 2; mi++) {
                    MMA_BF16(acc[mi][njp * 2],     ah[mi], bhf[0], bhf[1]);
                    MMA_BF16(acc[mi][njp * 2],     al[mi], bhf[0], bhf[1]);
                    MMA_BF16(acc[mi][njp * 2],     ah[mi], blf[0], blf[1]);
                    MMA_BF16(acc[mi][njp * 2 + 1], ah[mi], bhf[2], bhf[3]);
                    MMA_BF16(acc[mi][njp * 2 + 1], al[mi], bhf[2], bhf[3]);
                    MMA_BF16(acc[mi][njp * 2 + 1], ah[mi], blf[2], blf[3]);
                }
            }
        }
        __syncthreads();
    }

    // Epilogue: fp32 acc -> bf16 hi/lo pairs, head-split [b][h][s][hd]
    const int rr = lane >> 2;
    const int cc = (lane & 3) * 2;
#pragma unroll
    for (int mi = 0; mi < 2; mi++) {
#pragma unroll
        for (int nj = 0; nj < 8; nj++) {
            int n  = n0 + wn * 64 + nj * 8 + cc;
            int h  = n >> 6, hd = n & 63;
            int m  = m0 + wm * 32 + mi * 16 + rr;
            int bb = m >> 11, ss = m & 2047;
            size_t idx0 = (((size_t)(bb * NHEADS + h)) * SEQ + ss) * HDIM + hd;
#pragma unroll
            for (int half = 0; half < 2; half++) {   // rows m, m+8
                float v0 = acc[mi][nj][half * 2 + 0];
                float v1 = acc[mi][nj][half * 2 + 1];
                __nv_bfloat16 h0 = __float2bfloat16(v0);
                __nv_bfloat16 h1 = __float2bfloat16(v1);
                uint32_t uhi = (uint32_t)__bfloat16_as_ushort(h0) |
                               ((uint32_t)__bfloat16_as_ushort(h1) << 16);
                uint32_t ulo = pack_bf16(v0 - __bfloat162float(h0),
                                         v1 - __bfloat162float(h1));
                size_t idx = idx0 + (size_t)half * 8 * HDIM;
                *reinterpret_cast<uint32_t*>(OutHi + idx) = uhi;
                *reinterpret_cast<uint32_t*>(OutLo + idx) = ulo;
            }
        }
    }
}

// ===========================================================================
// Tensor-core flash attention (validated R4).
// Round 5 change: PV is 2-term (Phi*Vhi + Phi*Vlo); l sums the ROUNDED p
// values so P-quantization error cancels between numerator and denominator.
// ===========================================================================
#define AT_SMEM (32768 + 2 * 32768)

__global__ __launch_bounds__(256)
void attn_tc_kernel(const __nv_bfloat16* __restrict__ Qhi,
                    const __nv_bfloat16* __restrict__ Qlo,
                    const __nv_bfloat16* __restrict__ Khi,
                    const __nv_bfloat16* __restrict__ Klo,
                    const __nv_bfloat16* __restrict__ Vhi,
                    const __nv_bfloat16* __restrict__ Vlo,
                    float* __restrict__ Out)
{
    extern __shared__ char sma[];
    const uint32_t sm0 = smem_u32(sma);
    const int tid  = threadIdx.x;
    const int lane = tid & 31;
    const int wq   = tid >> 5;
    const int q0   = blockIdx.x * 128;
    const int h    = blockIdx.y;
    const int b    = blockIdx.z;
    const size_t base = ((size_t)(b * NHEADS + h)) * SEQ * HDIM;

    const uint4* gqh = (const uint4*)(Qhi + base + (size_t)q0 * HDIM);
    const uint4* gql = (const uint4*)(Qlo + base + (size_t)q0 * HDIM);
    const uint4* gkh = (const uint4*)(Khi + base);
    const uint4* gkl = (const uint4*)(Klo + base);
    const uint4* gvh = (const uint4*)(Vhi + base);
    const uint4* gvl = (const uint4*)(Vlo + base);

    // ---- load Q tile (128 x 64 bf16, hi+lo) into smem
#pragma unroll
    for (int i = 0; i < 4; i++) {
        int lin = tid + i * 256;
        int row = lin >> 3, col = lin & 7;
        uint32_t off = sw128(row * 128 + col * 16);
        *reinterpret_cast<uint4*>(sma + off)         = gqh[row * 8 + col];
        *reinterpret_cast<uint4*>(sma + 16384 + off) = gql[row * 8 + col];
    }

    auto kv_fill = [&](uint32_t dstbase, int kt) {
#pragma unroll
        for (int i = 0; i < 8; i++) {
            int lin = tid + i * 256;
            int mat = lin >> 9;
            int rem = lin & 511;
            int row = rem >> 3, col = rem & 7;
            const uint4* src =
                (mat == 0 ? gkh : mat == 1 ? gkl : mat == 2 ? gvh : gvl)
                + (size_t)(kt + row) * 8 + col;
            uint32_t dst = dstbase + mat * 8192 + sw128(row * 128 + col * 16);
            CP_A16(dst, src);
        }
    };
    kv_fill(sm0 + 32768, 0);
    CP_COMMIT();

    __syncthreads();   // Q smem ready

    const int rIn    = lane & 7;
    const int a_rsel = ((lane >> 3) & 1) * 8;
    const int a_ksel = ((lane >> 4) & 1) * 16;
    const int b_nsel = ((lane >> 4) & 1) * 8;
    const int b_ksel = ((lane >> 3) & 1) * 16;
    const int v_rsel = ((lane >> 3) & 1) * 8;
    const int v_nsel = ((lane >> 4) & 1) * 16;

    uint32_t qh[4][4], ql[4][4];
#pragma unroll
    for (int ks = 0; ks < 4; ks++) {
        uint32_t off = sw128((wq * 16 + a_rsel + rIn) * 128 + ks * 32 + a_ksel);
        LDSM_X4(qh[ks][0], qh[ks][1], qh[ks][2], qh[ks][3], sm0 + off);
        LDSM_X4(ql[ks][0], ql[ks][1], ql[ks][2], ql[ks][3], sm0 + 16384 + off);
    }

    float o[8][4];
#pragma unroll
    for (int v = 0; v < 8; v++)
#pragma unroll
        for (int e = 0; e < 4; e++) o[v][e] = 0.f;
    float m0r = -3.0e38f, m1r = -3.0e38f;
    float l0 = 0.f, l1 = 0.f;

    for (int t = 0; t < SEQ / 64; t++) {
        if (t + 1 < SEQ / 64) {
            kv_fill(sm0 + 32768 + ((t + 1) & 1) * 32768, (t + 1) * 64);
            CP_COMMIT();
            CP_WAIT(1);
        } else {
            CP_WAIT(0);
        }
        __syncthreads();
        const uint32_t kb = sm0 + 32768 + (t & 1) * 32768;
        const uint32_t vb = kb + 16384;

        // ---- S = Q K^T (3-term split), unscaled
        float s[8][4];
#pragma unroll
        for (int j = 0; j < 8; j++)
#pragma unroll
            for (int e = 0; e < 4; e++) s[j][e] = 0.f;
#pragma unroll
        for (int ks = 0; ks < 4; ks++) {
#pragma unroll
            for (int np = 0; np < 4; np++) {
                uint32_t off = sw128((np * 16 + b_nsel + rIn) * 128 + ks * 32 + b_ksel);
                uint32_t kf[4], lf[4];
                LDSM_X4(kf[0], kf[1], kf[2], kf[3], kb + off);
                LDSM_X4(lf[0], lf[1], lf[2], lf[3], kb + 8192 + off);
                MMA_BF16(s[np * 2],     qh[ks], kf[0], kf[1]);
                MMA_BF16(s[np * 2],     ql[ks], kf[0], kf[1]);
                MMA_BF16(s[np * 2],     qh[ks], lf[0], lf[1]);
                MMA_BF16(s[np * 2 + 1], qh[ks], kf[2], kf[3]);
                MMA_BF16(s[np * 2 + 1], ql[ks], kf[2], kf[3]);
                MMA_BF16(s[np * 2 + 1], qh[ks], lf[2], lf[3]);
            }
        }

        // ---- register softmax (rows r=lane>>2 and r+8), scaled domain x64
        float mt0 = -3.0e38f, mt1 = -3.0e38f;
#pragma unroll
        for (int j = 0; j < 8; j++) {
            mt0 = fmaxf(mt0, fmaxf(s[j][0], s[j][1]));
            mt1 = fmaxf(mt1, fmaxf(s[j][2], s[j][3]));
        }
        mt0 = fmaxf(mt0, __shfl_xor_sync(0xffffffffu, mt0, 1));
        mt0 = fmaxf(mt0, __shfl_xor_sync(0xffffffffu, mt0, 2));
        mt1 = fmaxf(mt1, __shfl_xor_sync(0xffffffffu, mt1, 1));
        mt1 = fmaxf(mt1, __shfl_xor_sync(0xffffffffu, mt1, 2));
        float M0 = fmaxf(m0r, mt0 * 64.f);
        float M1 = fmaxf(m1r, mt1 * 64.f);
        float a0 = __expf(m0r - M0);
        float a1 = __expf(m1r - M1);
        m0r = M0; m1r = M1;

        float rs0 = 0.f, rs1 = 0.f;
        uint32_t aphi[4][4];
#pragma unroll
        for (int jp = 0; jp < 4; jp++) {
#pragma unroll
            for (int half = 0; half < 2; half++) {   // frags 2jp, 2jp+1
                int j = jp * 2 + half;
                float p0 = __expf(fmaf(s[j][0], 64.f, -M0));
                float p1 = __expf(fmaf(s[j][1], 64.f, -M0));
                float p2 = __expf(fmaf(s[j][2], 64.f, -M1));
                float p3 = __expf(fmaf(s[j][3], 64.f, -M1));
                __nv_bfloat16 h0 = __float2bfloat16(p0);
                __nv_bfloat16 h1 = __float2bfloat16(p1);
                __nv_bfloat16 h2 = __float2bfloat16(p2);
                __nv_bfloat16 h3 = __float2bfloat16(p3);
                // l sums the ROUNDED p: quantization cancels in out = (P.V)/l
                rs0 += __bfloat162float(h0) + __bfloat162float(h1);
                rs1 += __bfloat162float(h2) + __bfloat162float(h3);
                aphi[jp][half * 2 + 0] =
                    (uint32_t)__bfloat16_as_ushort(h0) |
                    ((uint32_t)__bfloat16_as_ushort(h1) << 16);
                aphi[jp][half * 2 + 1] =
                    (uint32_t)__bfloat16_as_ushort(h2) |
                    ((uint32_t)__bfloat16_as_ushort(h3) << 16);
            }
        }

        rs0 += __shfl_xor_sync(0xffffffffu, rs0, 1);
        rs0 += __shfl_xor_sync(0xffffffffu, rs0, 2);
        rs1 += __shfl_xor_sync(0xffffffffu, rs1, 1);
        rs1 += __shfl_xor_sync(0xffffffffu, rs1, 2);
        l0 = l0 * a0 + rs0;
        l1 = l1 * a1 + rs1;
#pragma unroll
        for (int v = 0; v < 8; v++) {
            o[v][0] *= a0; o[v][1] *= a0;
            o[v][2] *= a1; o[v][3] *= a1;
        }

        // ---- O += P V (2-term: Phi*Vhi + Phi*Vlo), V via ldmatrix.trans
#pragma unroll
        for (int t4 = 0; t4 < 4; t4++) {
#pragma unroll
            for (int vp = 0; vp < 4; vp++) {
                uint32_t off = sw128((t4 * 16 + v_rsel + rIn) * 128 + vp * 32 + v_nsel);
                uint32_t vh[4], vl[4];
                LDSM_X4_T(vh[0], vh[1], vh[2], vh[3], vb + off);
                LDSM_X4_T(vl[0], vl[1], vl[2], vl[3], vb + 8192 + off);
                MMA_BF16(o[vp * 2],     aphi[t4], vh[0], vh[1]);
                MMA_BF16(o[vp * 2],     aphi[t4], vl[0], vl[1]);
                MMA_BF16(o[vp * 2 + 1], aphi[t4], vh[2], vh[3]);
                MMA_BF16(o[vp * 2 + 1], aphi[t4], vl[2], vl[3]);
            }
        }
        __syncthreads();   // all reads of this buffer done before refill
    }

    // ---- epilogue: normalize, write out[b][s][h*64+hd]
    float inv0 = 1.f / l0;
    float inv1 = 1.f / l1;
    int s0 = q0 + wq * 16 + (lane >> 2);
    int hd0 = h * 64 + 2 * (lane & 3);
#pragma unroll
    for (int v = 0; v < 8; v++) {
        float2 w0 = make_float2(o[v][0] * inv0, o[v][1] * inv0);
        float2 w1 = make_float2(o[v][2] * inv1, o[v][3] * inv1);
        *reinterpret_cast<float2*>(
            &Out[(size_t)(b * SEQ + s0) * DMODEL + hd0 + v * 8]) = w0;
        *reinterpret_cast<float2*>(
            &Out[(size_t)(b * SEQ + s0 + 8) * DMODEL + hd0 + v * 8]) = w1;
    }
}

// ---------------------------------------------------------------------------
extern "C" void kernel_launch(void* const* d_in, const int* in_sizes, int n_in,
                              void* d_out, int out_size)
{
    const float* q  = (const float*)d_in[0];
    const float* k  = (const float*)d_in[1];
    const float* v  = (const float*)d_in[2];
    const float* Wq = (const float*)d_in[3];
    const float* Wk = (const float*)d_in[4];
    const float* Wv = (const float*)d_in[5];
    float* out = (float*)d_out;

    __nv_bfloat16 *Qhi, *Qlo, *Khi, *Klo, *Vhi, *Vlo;
    cudaGetSymbolAddress((void**)&Qhi, g_Qhi);
    cudaGetSymbolAddress((void**)&Qlo, g_Qlo);
    cudaGetSymbolAddress((void**)&Khi, g_Khi);
    cudaGetSymbolAddress((void**)&Klo, g_Klo);
    cudaGetSymbolAddress((void**)&Vhi, g_Vhi);
    cudaGetSymbolAddress((void**)&Vlo, g_Vlo);

    cudaFuncSetAttribute(proj_mma_kernel,
                         cudaFuncAttributeMaxDynamicSharedMemorySize, PROJ_SMEM);
    cudaFuncSetAttribute(attn_tc_kernel,
                         cudaFuncAttributeMaxDynamicSharedMemorySize, AT_SMEM);

    dim3 pg(4096 / 128, 1024 / 128, 3);
    proj_mma_kernel<<<pg, 256, PROJ_SMEM>>>(q, k, v, Wq, Wk, Wv,
                                            Qhi, Qlo, Khi, Klo, Vhi, Vlo);

    dim3 ag(SEQ / 128, NHEADS, BATCH);   // (16, 16, 2)
    attn_tc_kernel<<<ag, 256, AT_SMEM>>>(Qhi, Qlo, Khi, Klo, Vhi, Vlo, out);
}

// round 7
// speedup vs baseline: 3.7211x; 1.1083x over previous
#include <cuda_runtime.h>
#include <cuda_bf16.h>
#include <cuda_fp16.h>
#include <cstdint>

// ---------------------------------------------------------------------------
// MultiHeadAttention: out = softmax((XQ Wq^T)(XK Wk^T)^T * 64) (XV Wv^T)
// b=2, s=2048, d=1024, heads=16, hd=64.
// Round 6: V chain in single-term fp16 (P fp16, l from rounded P cancels the
// quantization); exp via ex2.approx with folded 64*log2(e); proj LDG batching.
// ---------------------------------------------------------------------------

#define BATCH     2
#define SEQ       2048
#define DMODEL    1024
#define NHEADS    16
#define HDIM      64

// Projected Q/K head-split [b][h][s][hd], bf16 hi/lo; V as plain fp16
__device__ __nv_bfloat16 g_Qhi[BATCH * NHEADS * SEQ * HDIM];
__device__ __nv_bfloat16 g_Qlo[BATCH * NHEADS * SEQ * HDIM];
__device__ __nv_bfloat16 g_Khi[BATCH * NHEADS * SEQ * HDIM];
__device__ __nv_bfloat16 g_Klo[BATCH * NHEADS * SEQ * HDIM];
__device__ __half        g_Vh [BATCH * NHEADS * SEQ * HDIM];

#define EXP2_SCALE 92.33248261689366f   // 64 * log2(e)

__device__ __forceinline__ uint32_t smem_u32(const void* p) {
    uint32_t a;
    asm("{ .reg .u64 t; cvta.to.shared.u64 t, %1; cvt.u32.u64 %0, t; }"
        : "=r"(a) : "l"(p));
    return a;
}
__device__ __forceinline__ uint32_t sw128(uint32_t b) {
    return b ^ ((b >> 3) & 0x70);
}
__device__ __forceinline__ float ex2f(float x) {
    float y;
    asm("ex2.approx.f32 %0, %1;" : "=f"(y) : "f"(x));
    return y;
}

#define LDSM_X4(r0, r1, r2, r3, addr) \
    asm volatile("ldmatrix.sync.aligned.m8n8.x4.shared.b16 {%0,%1,%2,%3}, [%4];" \
                 : "=r"(r0), "=r"(r1), "=r"(r2), "=r"(r3) : "r"(addr))
#define LDSM_X4_T(r0, r1, r2, r3, addr) \
    asm volatile("ldmatrix.sync.aligned.m8n8.x4.trans.shared.b16 {%0,%1,%2,%3}, [%4];" \
                 : "=r"(r0), "=r"(r1), "=r"(r2), "=r"(r3) : "r"(addr))

#define MMA_BF16(d, a, b0, b1) \
    asm volatile("mma.sync.aligned.m16n8k16.row.col.f32.bf16.bf16.f32 " \
                 "{%0,%1,%2,%3}, {%4,%5,%6,%7}, {%8,%9}, {%0,%1,%2,%3};" \
                 : "+f"((d)[0]), "+f"((d)[1]), "+f"((d)[2]), "+f"((d)[3]) \
                 : "r"((a)[0]), "r"((a)[1]), "r"((a)[2]), "r"((a)[3]), \
                   "r"(b0), "r"(b1))
#define MMA_F16(d, a, b0, b1) \
    asm volatile("mma.sync.aligned.m16n8k16.row.col.f32.f16.f16.f32 " \
                 "{%0,%1,%2,%3}, {%4,%5,%6,%7}, {%8,%9}, {%0,%1,%2,%3};" \
                 : "+f"((d)[0]), "+f"((d)[1]), "+f"((d)[2]), "+f"((d)[3]) \
                 : "r"((a)[0]), "r"((a)[1]), "r"((a)[2]), "r"((a)[3]), \
                   "r"(b0), "r"(b1))

#define CP_A16(dst, src) \
    asm volatile("cp.async.cg.shared.global [%0], [%1], 16;" \
                 :: "r"(dst), "l"(src) : "memory")
#define CP_COMMIT() asm volatile("cp.async.commit_group;" ::: "memory")
#define CP_WAIT(n)  asm volatile("cp.async.wait_group %0;" :: "n"(n) : "memory")

__device__ __forceinline__ uint32_t pack_bf16(float lo, float hi) {
    uint32_t u = (uint32_t)__bfloat16_as_ushort(__float2bfloat16(lo)) |
                 ((uint32_t)__bfloat16_as_ushort(__float2bfloat16(hi)) << 16);
    return u;
}

// ===========================================================================
// Projection GEMM via mma.sync (validated R3-R5). bf16x2 split fused into the
// tile load with batched LDG issue. z==2 (V) epilogue emits plain fp16.
// ===========================================================================
#define PROJ_SMEM (4 * 16384)

__device__ __forceinline__ void load_split_tile(const float* __restrict__ g,
                                                int row0, int kcol0,
                                                char* smHi, char* smLo, int tid)
{
    float4 va[8];
#pragma unroll
    for (int q = 0; q < 4; q++) {
        int lin = tid + q * 256;
        int row = lin >> 3, cg = lin & 7;
        const float4* src = reinterpret_cast<const float4*>(
            g + (size_t)(row0 + row) * DMODEL + kcol0 + cg * 8);
        va[2 * q]     = src[0];
        va[2 * q + 1] = src[1];
    }
#pragma unroll
    for (int q = 0; q < 4; q++) {
        int lin = tid + q * 256;
        int row = lin >> 3, cg = lin & 7;
        float xs[8] = {va[2*q].x, va[2*q].y, va[2*q].z, va[2*q].w,
                       va[2*q+1].x, va[2*q+1].y, va[2*q+1].z, va[2*q+1].w};
        uint32_t hw[4], lw[4];
#pragma unroll
        for (int j = 0; j < 4; j++) {
            __nv_bfloat16 h0 = __float2bfloat16(xs[j * 2]);
            __nv_bfloat16 h1 = __float2bfloat16(xs[j * 2 + 1]);
            hw[j] = (uint32_t)__bfloat16_as_ushort(h0) |
                    ((uint32_t)__bfloat16_as_ushort(h1) << 16);
            lw[j] = pack_bf16(xs[j * 2] - __bfloat162float(h0),
                              xs[j * 2 + 1] - __bfloat162float(h1));
        }
        uint32_t off = sw128(row * 128 + cg * 16);
        *reinterpret_cast<uint4*>(smHi + off) = make_uint4(hw[0], hw[1], hw[2], hw[3]);
        *reinterpret_cast<uint4*>(smLo + off) = make_uint4(lw[0], lw[1], lw[2], lw[3]);
    }
}

__global__ __launch_bounds__(256, 2)
void proj_mma_kernel(const float* __restrict__ Xq, const float* __restrict__ Xk,
                     const float* __restrict__ Xv,
                     const float* __restrict__ Wq, const float* __restrict__ Wk,
                     const float* __restrict__ Wv,
                     __nv_bfloat16* __restrict__ Qhi, __nv_bfloat16* __restrict__ Qlo,
                     __nv_bfloat16* __restrict__ Khi, __nv_bfloat16* __restrict__ Klo,
                     __half* __restrict__ Vh)
{
    extern __shared__ char smp[];
    char* Ah = smp;
    char* Al = smp + 16384;
    char* Bh = smp + 32768;
    char* Bl = smp + 49152;
    const uint32_t ah_u = smem_u32(Ah), al_u = smem_u32(Al);
    const uint32_t bh_u = smem_u32(Bh), bl_u = smem_u32(Bl);

    const int tid  = threadIdx.x;
    const int wid  = tid >> 5, lane = tid & 31;
    const int wm   = wid >> 1;
    const int wn   = wid & 1;
    const int m0   = blockIdx.x * 128;
    const int n0   = blockIdx.y * 128;
    const int z    = blockIdx.z;

    const float* X = (z == 0) ? Xq : ((z == 1) ? Xk : Xv);
    const float* W = (z == 0) ? Wq : ((z == 1) ? Wk : Wv);
    __nv_bfloat16* OutHi = (z == 0) ? Qhi : Khi;
    __nv_bfloat16* OutLo = (z == 0) ? Qlo : Klo;

    float acc[2][8][4];
#pragma unroll
    for (int i = 0; i < 2; i++)
#pragma unroll
        for (int j = 0; j < 8; j++)
#pragma unroll
            for (int e = 0; e < 4; e++) acc[i][j][e] = 0.f;

    const int rIn    = lane & 7;
    const int a_rsel = ((lane >> 3) & 1) * 8;
    const int a_ksel = ((lane >> 4) & 1) * 16;
    const int b_nsel = ((lane >> 4) & 1) * 8;
    const int b_ksel = ((lane >> 3) & 1) * 16;

    for (int c = 0; c < DMODEL / 64; c++) {
        const int k0 = c * 64;
        load_split_tile(X, m0, k0, Ah, Al, tid);
        load_split_tile(W, n0, k0, Bh, Bl, tid);
        __syncthreads();

#pragma unroll
        for (int ks = 0; ks < 4; ks++) {
            uint32_t ah[2][4], al[2][4];
#pragma unroll
            for (int mi = 0; mi < 2; mi++) {
                int row = wm * 32 + mi * 16 + a_rsel + rIn;
                uint32_t off = sw128(row * 128 + ks * 32 + a_ksel);
                LDSM_X4(ah[mi][0], ah[mi][1], ah[mi][2], ah[mi][3], ah_u + off);
                LDSM_X4(al[mi][0], al[mi][1], al[mi][2], al[mi][3], al_u + off);
            }
#pragma unroll
            for (int njp = 0; njp < 4; njp++) {
                int nrow = wn * 64 + njp * 16 + b_nsel + rIn;
                uint32_t off = sw128(nrow * 128 + ks * 32 + b_ksel);
                uint32_t bhf[4], blf[4];
                LDSM_X4(bhf[0], bhf[1], bhf[2], bhf[3], bh_u + off);
                LDSM_X4(blf[0], blf[1], blf[2], blf[3], bl_u + off);
#pragma unroll
                for (int mi = 0; mi < 2; mi++) {
                    MMA_BF16(acc[mi][njp * 2],     ah[mi], bhf[0], bhf[1]);
                    MMA_BF16(acc[mi][njp * 2],     al[mi], bhf[0], bhf[1]);
                    MMA_BF16(acc[mi][njp * 2],     ah[mi], blf[0], blf[1]);
                    MMA_BF16(acc[mi][njp * 2 + 1], ah[mi], bhf[2], bhf[3]);
                    MMA_BF16(acc[mi][njp * 2 + 1], al[mi], bhf[2], bhf[3]);
                    MMA_BF16(acc[mi][njp * 2 + 1], ah[mi], blf[2], blf[3]);
                }
            }
        }
        __syncthreads();
    }

    // Epilogue: head-split [b][h][s][hd]; Q/K -> bf16 hi/lo, V -> fp16
    const int rr = lane >> 2;
    const int cc = (lane & 3) * 2;
#pragma unroll
    for (int mi = 0; mi < 2; mi++) {
#pragma unroll
        for (int nj = 0; nj < 8; nj++) {
            int n  = n0 + wn * 64 + nj * 8 + cc;
            int h  = n >> 6, hd = n & 63;
            int m  = m0 + wm * 32 + mi * 16 + rr;
            int bb = m >> 11, ss = m & 2047;
            size_t idx0 = (((size_t)(bb * NHEADS + h)) * SEQ + ss) * HDIM + hd;
#pragma unroll
            for (int half_i = 0; half_i < 2; half_i++) {   // rows m, m+8
                float v0 = acc[mi][nj][half_i * 2 + 0];
                float v1 = acc[mi][nj][half_i * 2 + 1];
                size_t idx = idx0 + (size_t)half_i * 8 * HDIM;
                if (z == 2) {
                    __half2 hv = __floats2half2_rn(v0, v1);
                    *reinterpret_cast<__half2*>(Vh + idx) = hv;
                } else {
                    __nv_bfloat16 h0 = __float2bfloat16(v0);
                    __nv_bfloat16 h1 = __float2bfloat16(v1);
                    uint32_t uhi = (uint32_t)__bfloat16_as_ushort(h0) |
                                   ((uint32_t)__bfloat16_as_ushort(h1) << 16);
                    uint32_t ulo = pack_bf16(v0 - __bfloat162float(h0),
                                             v1 - __bfloat162float(h1));
                    *reinterpret_cast<uint32_t*>(OutHi + idx) = uhi;
                    *reinterpret_cast<uint32_t*>(OutLo + idx) = ulo;
                }
            }
        }
    }
}

// ===========================================================================
// Tensor-core flash attention (validated R4/R5).
// Round 6: PV = single fp16 term (P fp16, V fp16); exp via ex2.approx with
// folded 64*log2e; KV tile = Khi/Klo bf16 + V fp16 (24 KB), double-buffered.
// SMEM: Q 32KB | 2 x 24KB = 80 KB.
// ===========================================================================
#define AT_SMEM (32768 + 2 * 24576)

__global__ __launch_bounds__(256)
void attn_tc_kernel(const __nv_bfloat16* __restrict__ Qhi,
                    const __nv_bfloat16* __restrict__ Qlo,
                    const __nv_bfloat16* __restrict__ Khi,
                    const __nv_bfloat16* __restrict__ Klo,
                    const __half* __restrict__ Vh,
                    float* __restrict__ Out)
{
    extern __shared__ char sma[];
    const uint32_t sm0 = smem_u32(sma);
    const int tid  = threadIdx.x;
    const int lane = tid & 31;
    const int wq   = tid >> 5;
    const int q0   = blockIdx.x * 128;
    const int h    = blockIdx.y;
    const int b    = blockIdx.z;
    const size_t base = ((size_t)(b * NHEADS + h)) * SEQ * HDIM;

    const uint4* gqh = (const uint4*)(Qhi + base + (size_t)q0 * HDIM);
    const uint4* gql = (const uint4*)(Qlo + base + (size_t)q0 * HDIM);
    const uint4* gkh = (const uint4*)(Khi + base);
    const uint4* gkl = (const uint4*)(Klo + base);
    const uint4* gvh = (const uint4*)(Vh  + base);

    // ---- load Q tile (128 x 64 bf16, hi+lo) into smem
#pragma unroll
    for (int i = 0; i < 4; i++) {
        int lin = tid + i * 256;
        int row = lin >> 3, col = lin & 7;
        uint32_t off = sw128(row * 128 + col * 16);
        *reinterpret_cast<uint4*>(sma + off)         = gqh[row * 8 + col];
        *reinterpret_cast<uint4*>(sma + 16384 + off) = gql[row * 8 + col];
    }

    // K hi (8K) + K lo (8K) + V fp16 (8K) per stage
    auto kv_fill = [&](uint32_t dstbase, int kt) {
#pragma unroll
        for (int i = 0; i < 6; i++) {
            int lin = tid + i * 256;
            int mat = lin >> 9;                 // 0: Khi, 1: Klo, 2: V
            int rem = lin & 511;
            int row = rem >> 3, col = rem & 7;
            const uint4* src =
                (mat == 0 ? gkh : mat == 1 ? gkl : gvh)
                + (size_t)(kt + row) * 8 + col;
            uint32_t dst = dstbase + mat * 8192 + sw128(row * 128 + col * 16);
            CP_A16(dst, src);
        }
    };
    kv_fill(sm0 + 32768, 0);
    CP_COMMIT();

    __syncthreads();   // Q smem ready

    const int rIn    = lane & 7;
    const int a_rsel = ((lane >> 3) & 1) * 8;
    const int a_ksel = ((lane >> 4) & 1) * 16;
    const int b_nsel = ((lane >> 4) & 1) * 8;
    const int b_ksel = ((lane >> 3) & 1) * 16;
    const int v_rsel = ((lane >> 3) & 1) * 8;
    const int v_nsel = ((lane >> 4) & 1) * 16;

    uint32_t qh[4][4], ql[4][4];
#pragma unroll
    for (int ks = 0; ks < 4; ks++) {
        uint32_t off = sw128((wq * 16 + a_rsel + rIn) * 128 + ks * 32 + a_ksel);
        LDSM_X4(qh[ks][0], qh[ks][1], qh[ks][2], qh[ks][3], sm0 + off);
        LDSM_X4(ql[ks][0], ql[ks][1], ql[ks][2], ql[ks][3], sm0 + 16384 + off);
    }

    float o[8][4];
#pragma unroll
    for (int v = 0; v < 8; v++)
#pragma unroll
        for (int e = 0; e < 4; e++) o[v][e] = 0.f;
    float m0r = -3.0e38f, m1r = -3.0e38f;   // log2-domain running max
    float l0 = 0.f, l1 = 0.f;

    for (int t = 0; t < SEQ / 64; t++) {
        if (t + 1 < SEQ / 64) {
            kv_fill(sm0 + 32768 + ((t + 1) & 1) * 24576, (t + 1) * 64);
            CP_COMMIT();
            CP_WAIT(1);
        } else {
            CP_WAIT(0);
        }
        __syncthreads();
        const uint32_t kb = sm0 + 32768 + (t & 1) * 24576;
        const uint32_t vb = kb + 16384;

        // ---- S = Q K^T (3-term bf16 split), raw dot domain
        float s[8][4];
#pragma unroll
        for (int j = 0; j < 8; j++)
#pragma unroll
            for (int e = 0; e < 4; e++) s[j][e] = 0.f;
#pragma unroll
        for (int ks = 0; ks < 4; ks++) {
#pragma unroll
            for (int np = 0; np < 4; np++) {
                uint32_t off = sw128((np * 16 + b_nsel + rIn) * 128 + ks * 32 + b_ksel);
                uint32_t kf[4], lf[4];
                LDSM_X4(kf[0], kf[1], kf[2], kf[3], kb + off);
                LDSM_X4(lf[0], lf[1], lf[2], lf[3], kb + 8192 + off);
                MMA_BF16(s[np * 2],     qh[ks], kf[0], kf[1]);
                MMA_BF16(s[np * 2],     ql[ks], kf[0], kf[1]);
                MMA_BF16(s[np * 2],     qh[ks], lf[0], lf[1]);
                MMA_BF16(s[np * 2 + 1], qh[ks], kf[2], kf[3]);
                MMA_BF16(s[np * 2 + 1], ql[ks], kf[2], kf[3]);
                MMA_BF16(s[np * 2 + 1], qh[ks], lf[2], lf[3]);
            }
        }

        // ---- softmax in exp2 domain: weight = 2^(s*C - M2)
        float mt0 = -3.0e38f, mt1 = -3.0e38f;
#pragma unroll
        for (int j = 0; j < 8; j++) {
            mt0 = fmaxf(mt0, fmaxf(s[j][0], s[j][1]));
            mt1 = fmaxf(mt1, fmaxf(s[j][2], s[j][3]));
        }
        mt0 = fmaxf(mt0, __shfl_xor_sync(0xffffffffu, mt0, 1));
        mt0 = fmaxf(mt0, __shfl_xor_sync(0xffffffffu, mt0, 2));
        mt1 = fmaxf(mt1, __shfl_xor_sync(0xffffffffu, mt1, 1));
        mt1 = fmaxf(mt1, __shfl_xor_sync(0xffffffffu, mt1, 2));
        float M0 = fmaxf(m0r, mt0 * EXP2_SCALE);
        float M1 = fmaxf(m1r, mt1 * EXP2_SCALE);
        float a0 = ex2f(m0r - M0);
        float a1 = ex2f(m1r - M1);
        m0r = M0; m1r = M1;

        float rs0 = 0.f, rs1 = 0.f;
        uint32_t ap[4][4];   // P fragments, fp16
#pragma unroll
        for (int jp = 0; jp < 4; jp++) {
#pragma unroll
            for (int half_i = 0; half_i < 2; half_i++) {
                int j = jp * 2 + half_i;
                float p0 = ex2f(fmaf(s[j][0], EXP2_SCALE, -M0));
                float p1 = ex2f(fmaf(s[j][1], EXP2_SCALE, -M0));
                float p2 = ex2f(fmaf(s[j][2], EXP2_SCALE, -M1));
                float p3 = ex2f(fmaf(s[j][3], EXP2_SCALE, -M1));
                __half2 h01 = __floats2half2_rn(p0, p1);
                __half2 h23 = __floats2half2_rn(p2, p3);
                // l sums the ROUNDED p: quantization cancels in out = (P.V)/l
                float2 f01 = __half22float2(h01);
                float2 f23 = __half22float2(h23);
                rs0 += f01.x + f01.y;
                rs1 += f23.x + f23.y;
                ap[jp][half_i * 2 + 0] = *reinterpret_cast<uint32_t*>(&h01);
                ap[jp][half_i * 2 + 1] = *reinterpret_cast<uint32_t*>(&h23);
            }
        }

        rs0 += __shfl_xor_sync(0xffffffffu, rs0, 1);
        rs0 += __shfl_xor_sync(0xffffffffu, rs0, 2);
        rs1 += __shfl_xor_sync(0xffffffffu, rs1, 1);
        rs1 += __shfl_xor_sync(0xffffffffu, rs1, 2);
        l0 = l0 * a0 + rs0;
        l1 = l1 * a1 + rs1;
#pragma unroll
        for (int v = 0; v < 8; v++) {
            o[v][0] *= a0; o[v][1] *= a0;
            o[v][2] *= a1; o[v][3] *= a1;
        }

        // ---- O += P V (single fp16 term), V via ldmatrix.trans
#pragma unroll
        for (int t4 = 0; t4 < 4; t4++) {
#pragma unroll
            for (int vp = 0; vp < 4; vp++) {
                uint32_t off = sw128((t4 * 16 + v_rsel + rIn) * 128 + vp * 32 + v_nsel);
                uint32_t vf[4];
                LDSM_X4_T(vf[0], vf[1], vf[2], vf[3], vb + off);
                MMA_F16(o[vp * 2],     ap[t4], vf[0], vf[1]);
                MMA_F16(o[vp * 2 + 1], ap[t4], vf[2], vf[3]);
            }
        }
        __syncthreads();   // all reads of this buffer done before refill
    }

    // ---- epilogue: normalize, write out[b][s][h*64+hd]
    float inv0 = 1.f / l0;
    float inv1 = 1.f / l1;
    int s0 = q0 + wq * 16 + (lane >> 2);
    int hd0 = h * 64 + 2 * (lane & 3);
#pragma unroll
    for (int v = 0; v < 8; v++) {
        float2 w0 = make_float2(o[v][0] * inv0, o[v][1] * inv0);
        float2 w1 = make_float2(o[v][2] * inv1, o[v][3] * inv1);
        *reinterpret_cast<float2*>(
            &Out[(size_t)(b * SEQ + s0) * DMODEL + hd0 + v * 8]) = w0;
        *reinterpret_cast<float2*>(
            &Out[(size_t)(b * SEQ + s0 + 8) * DMODEL + hd0 + v * 8]) = w1;
    }
}

// ---------------------------------------------------------------------------
extern "C" void kernel_launch(void* const* d_in, const int* in_sizes, int n_in,
                              void* d_out, int out_size)
{
    const float* q  = (const float*)d_in[0];
    const float* k  = (const float*)d_in[1];
    const float* v  = (const float*)d_in[2];
    const float* Wq = (const float*)d_in[3];
    const float* Wk = (const float*)d_in[4];
    const float* Wv = (const float*)d_in[5];
    float* out = (float*)d_out;

    __nv_bfloat16 *Qhi, *Qlo, *Khi, *Klo;
    __half *Vh;
    cudaGetSymbolAddress((void**)&Qhi, g_Qhi);
    cudaGetSymbolAddress((void**)&Qlo, g_Qlo);
    cudaGetSymbolAddress((void**)&Khi, g_Khi);
    cudaGetSymbolAddress((void**)&Klo, g_Klo);
    cudaGetSymbolAddress((void**)&Vh,  g_Vh);

    cudaFuncSetAttribute(proj_mma_kernel,
                         cudaFuncAttributeMaxDynamicSharedMemorySize, PROJ_SMEM);
    cudaFuncSetAttribute(attn_tc_kernel,
                         cudaFuncAttributeMaxDynamicSharedMemorySize, AT_SMEM);

    dim3 pg(4096 / 128, 1024 / 128, 3);
    proj_mma_kernel<<<pg, 256, PROJ_SMEM>>>(q, k, v, Wq, Wk, Wv,
                                            Qhi, Qlo, Khi, Klo, Vh);

    dim3 ag(SEQ / 128, NHEADS, BATCH);   // (16, 16, 2)
    attn_tc_kernel<<<ag, 256, AT_SMEM>>>(Qhi, Qlo, Khi, Klo, Vh, out);
}

// round 8
// speedup vs baseline: 4.1229x; 1.1080x over previous
#include <cuda_runtime.h>
#include <cuda_bf16.h>
#include <cuda_fp16.h>
#include <cstdint>

// ---------------------------------------------------------------------------
// MultiHeadAttention: out = softmax((XQ Wq^T)(XK Wk^T)^T * 64) (XV Wv^T)
// b=2, s=2048, d=1024, heads=16, hd=64.
// Round 7: projection pipelined - pre-split X/W (bf16 hi/lo) in gmem, proj
// consumes them via cp.async double-buffered smem (attn-style fill), MMA
// overlaps loads. Attention unchanged from R6.
// ---------------------------------------------------------------------------

#define BATCH     2
#define SEQ       2048
#define DMODEL    1024
#define NHEADS    16
#define HDIM      64

// bf16x2 split of raw inputs/weights
__device__ __nv_bfloat16 g_Xhi[3ull * 4096 * 1024];
__device__ __nv_bfloat16 g_Xlo[3ull * 4096 * 1024];
__device__ __nv_bfloat16 g_Whi[3ull * 1024 * 1024];
__device__ __nv_bfloat16 g_Wlo[3ull * 1024 * 1024];
// Projected Q/K head-split [b][h][s][hd], bf16 hi/lo; V as plain fp16
__device__ __nv_bfloat16 g_Qhi[BATCH * NHEADS * SEQ * HDIM];
__device__ __nv_bfloat16 g_Qlo[BATCH * NHEADS * SEQ * HDIM];
__device__ __nv_bfloat16 g_Khi[BATCH * NHEADS * SEQ * HDIM];
__device__ __nv_bfloat16 g_Klo[BATCH * NHEADS * SEQ * HDIM];
__device__ __half        g_Vh [BATCH * NHEADS * SEQ * HDIM];

#define EXP2_SCALE 92.33248261689366f   // 64 * log2(e)

__device__ __forceinline__ uint32_t smem_u32(const void* p) {
    uint32_t a;
    asm("{ .reg .u64 t; cvta.to.shared.u64 t, %1; cvt.u32.u64 %0, t; }"
        : "=r"(a) : "l"(p));
    return a;
}
__device__ __forceinline__ uint32_t sw128(uint32_t b) {
    return b ^ ((b >> 3) & 0x70);
}
__device__ __forceinline__ float ex2f(float x) {
    float y;
    asm("ex2.approx.f32 %0, %1;" : "=f"(y) : "f"(x));
    return y;
}

#define LDSM_X4(r0, r1, r2, r3, addr) \
    asm volatile("ldmatrix.sync.aligned.m8n8.x4.shared.b16 {%0,%1,%2,%3}, [%4];" \
                 : "=r"(r0), "=r"(r1), "=r"(r2), "=r"(r3) : "r"(addr))
#define LDSM_X4_T(r0, r1, r2, r3, addr) \
    asm volatile("ldmatrix.sync.aligned.m8n8.x4.trans.shared.b16 {%0,%1,%2,%3}, [%4];" \
                 : "=r"(r0), "=r"(r1), "=r"(r2), "=r"(r3) : "r"(addr))

#define MMA_BF16(d, a, b0, b1) \
    asm volatile("mma.sync.aligned.m16n8k16.row.col.f32.bf16.bf16.f32 " \
                 "{%0,%1,%2,%3}, {%4,%5,%6,%7}, {%8,%9}, {%0,%1,%2,%3};" \
                 : "+f"((d)[0]), "+f"((d)[1]), "+f"((d)[2]), "+f"((d)[3]) \
                 : "r"((a)[0]), "r"((a)[1]), "r"((a)[2]), "r"((a)[3]), \
                   "r"(b0), "r"(b1))
#define MMA_F16(d, a, b0, b1) \
    asm volatile("mma.sync.aligned.m16n8k16.row.col.f32.f16.f16.f32 " \
                 "{%0,%1,%2,%3}, {%4,%5,%6,%7}, {%8,%9}, {%0,%1,%2,%3};" \
                 : "+f"((d)[0]), "+f"((d)[1]), "+f"((d)[2]), "+f"((d)[3]) \
                 : "r"((a)[0]), "r"((a)[1]), "r"((a)[2]), "r"((a)[3]), \
                   "r"(b0), "r"(b1))

#define CP_A16(dst, src) \
    asm volatile("cp.async.cg.shared.global [%0], [%1], 16;" \
                 :: "r"(dst), "l"(src) : "memory")
#define CP_COMMIT() asm volatile("cp.async.commit_group;" ::: "memory")
#define CP_WAIT(n)  asm volatile("cp.async.wait_group %0;" :: "n"(n) : "memory")

__device__ __forceinline__ uint32_t pack_bf16(float lo, float hi) {
    uint32_t u = (uint32_t)__bfloat16_as_ushort(__float2bfloat16(lo)) |
                 ((uint32_t)__bfloat16_as_ushort(__float2bfloat16(hi)) << 16);
    return u;
}

// ===========================================================================
// Split kernel: x -> (bf16 hi, bf16 lo)  [proven in R3/R4]
// ===========================================================================
__global__ void split_kernel(const float4* __restrict__ src,
                             __nv_bfloat16* __restrict__ hi,
                             __nv_bfloat16* __restrict__ lo, int n4)
{
    int i = blockIdx.x * 256 + threadIdx.x;
    if (i >= n4) return;
    float4 v = src[i];
    float xs[4] = {v.x, v.y, v.z, v.w};
    uint32_t hb[4], lb[4];
#pragma unroll
    for (int j = 0; j < 4; j++) {
        __nv_bfloat16 h = __float2bfloat16(xs[j]);
        __nv_bfloat16 l = __float2bfloat16(xs[j] - __bfloat162float(h));
        hb[j] = (uint32_t)__bfloat16_as_ushort(h);
        lb[j] = (uint32_t)__bfloat16_as_ushort(l);
    }
    uint2 hp, lp;
    hp.x = hb[0] | (hb[1] << 16); hp.y = hb[2] | (hb[3] << 16);
    lp.x = lb[0] | (lb[1] << 16); lp.y = lb[2] | (lb[3] << 16);
    reinterpret_cast<uint2*>(hi)[i] = hp;
    reinterpret_cast<uint2*>(lo)[i] = lp;
}

// ===========================================================================
// Projection GEMM, cp.async double-buffered.
// CTA tile 128x128, K-chunk 64. Stage = Ahi|Alo|Bhi|Blo (4 x 16KB) = 64KB,
// two stages = 128KB -> 1 CTA/SM. MMA body identical to R5/R6 (proven).
// z==2 (V) epilogue emits plain fp16.
// ===========================================================================
#define PROJ_STAGE 65536
#define PROJ_SMEM  (2 * PROJ_STAGE)

__global__ __launch_bounds__(256)
void proj_mma_kernel(const __nv_bfloat16* __restrict__ Xhi_all,
                     const __nv_bfloat16* __restrict__ Xlo_all,
                     const __nv_bfloat16* __restrict__ Whi_all,
                     const __nv_bfloat16* __restrict__ Wlo_all,
                     __nv_bfloat16* __restrict__ Qhi, __nv_bfloat16* __restrict__ Qlo,
                     __nv_bfloat16* __restrict__ Khi, __nv_bfloat16* __restrict__ Klo,
                     __half* __restrict__ Vh)
{
    extern __shared__ char smp[];
    const uint32_t sm0 = smem_u32(smp);

    const int tid  = threadIdx.x;
    const int wid  = tid >> 5, lane = tid & 31;
    const int wm   = wid >> 1;
    const int wn   = wid & 1;
    const int m0   = blockIdx.x * 128;
    const int n0   = blockIdx.y * 128;
    const int z    = blockIdx.z;

    const uint4* gAh = (const uint4*)(Xhi_all + (size_t)z * 4096 * 1024 + (size_t)m0 * 1024);
    const uint4* gAl = (const uint4*)(Xlo_all + (size_t)z * 4096 * 1024 + (size_t)m0 * 1024);
    const uint4* gBh = (const uint4*)(Whi_all + (size_t)z * 1024 * 1024 + (size_t)n0 * 1024);
    const uint4* gBl = (const uint4*)(Wlo_all + (size_t)z * 1024 * 1024 + (size_t)n0 * 1024);

    // Fill stage (c&1) with chunk c: 4 tiles x 128 rows x 8 x 16B
    auto fill = [&](int c) {
        uint32_t sb = sm0 + (c & 1) * PROJ_STAGE;
#pragma unroll
        for (int i = 0; i < 16; i++) {
            int lin = tid + i * 256;
            int mat = lin >> 10;            // 0:Ahi 1:Alo 2:Bhi 3:Blo
            int rem = lin & 1023;
            int row = rem >> 3, col = rem & 7;
            const uint4* src =
                (mat == 0 ? gAh : mat == 1 ? gAl : mat == 2 ? gBh : gBl)
                + (size_t)row * 128 + c * 8 + col;
            uint32_t dst = sb + mat * 16384 + sw128(row * 128 + col * 16);
            CP_A16(dst, src);
        }
    };

    float acc[2][8][4];
#pragma unroll
    for (int i = 0; i < 2; i++)
#pragma unroll
        for (int j = 0; j < 8; j++)
#pragma unroll
            for (int e = 0; e < 4; e++) acc[i][j][e] = 0.f;

    const int rIn    = lane & 7;
    const int a_rsel = ((lane >> 3) & 1) * 8;
    const int a_ksel = ((lane >> 4) & 1) * 16;
    const int b_nsel = ((lane >> 4) & 1) * 8;
    const int b_ksel = ((lane >> 3) & 1) * 16;

    fill(0);
    CP_COMMIT();

    for (int c = 0; c < DMODEL / 64; c++) {
        if (c + 1 < DMODEL / 64) {
            fill(c + 1);
            CP_COMMIT();
            CP_WAIT(1);
        } else {
            CP_WAIT(0);
        }
        __syncthreads();

        const uint32_t st = sm0 + (c & 1) * PROJ_STAGE;
        const uint32_t ah_u = st, al_u = st + 16384;
        const uint32_t bh_u = st + 32768, bl_u = st + 49152;

#pragma unroll
        for (int ks = 0; ks < 4; ks++) {
            uint32_t ah[2][4], al[2][4];
#pragma unroll
            for (int mi = 0; mi < 2; mi++) {
                int row = wm * 32 + mi * 16 + a_rsel + rIn;
                uint32_t off = sw128(row * 128 + ks * 32 + a_ksel);
                LDSM_X4(ah[mi][0], ah[mi][1], ah[mi][2], ah[mi][3], ah_u + off);
                LDSM_X4(al[mi][0], al[mi][1], al[mi][2], al[mi][3], al_u + off);
            }
#pragma unroll
            for (int njp = 0; njp < 4; njp++) {
                int nrow = wn * 64 + njp * 16 + b_nsel + rIn;
                uint32_t off = sw128(nrow * 128 + ks * 32 + b_ksel);
                uint32_t bhf[4], blf[4];
                LDSM_X4(bhf[0], bhf[1], bhf[2], bhf[3], bh_u + off);
                LDSM_X4(blf[0], blf[1], blf[2], blf[3], bl_u + off);
#pragma unroll
                for (int mi = 0; mi < 2; mi++) {
                    MMA_BF16(acc[mi][njp * 2],     ah[mi], bhf[0], bhf[1]);
                    MMA_BF16(acc[mi][njp * 2],     al[mi], bhf[0], bhf[1]);
                    MMA_BF16(acc[mi][njp * 2],     ah[mi], blf[0], blf[1]);
                    MMA_BF16(acc[mi][njp * 2 + 1], ah[mi], bhf[2], bhf[3]);
                    MMA_BF16(acc[mi][njp * 2 + 1], al[mi], bhf[2], bhf[3]);
                    MMA_BF16(acc[mi][njp * 2 + 1], ah[mi], blf[2], blf[3]);
                }
            }
        }
        __syncthreads();
    }

    // Epilogue: head-split [b][h][s][hd]; Q/K -> bf16 hi/lo, V -> fp16
    const int rr = lane >> 2;
    const int cc = (lane & 3) * 2;
    __nv_bfloat16* OutHi = (z == 0) ? Qhi : Khi;
    __nv_bfloat16* OutLo = (z == 0) ? Qlo : Klo;
#pragma unroll
    for (int mi = 0; mi < 2; mi++) {
#pragma unroll
        for (int nj = 0; nj < 8; nj++) {
            int n  = n0 + wn * 64 + nj * 8 + cc;
            int h  = n >> 6, hd = n & 63;
            int m  = m0 + wm * 32 + mi * 16 + rr;
            int bb = m >> 11, ss = m & 2047;
            size_t idx0 = (((size_t)(bb * NHEADS + h)) * SEQ + ss) * HDIM + hd;
#pragma unroll
            for (int half_i = 0; half_i < 2; half_i++) {   // rows m, m+8
                float v0 = acc[mi][nj][half_i * 2 + 0];
                float v1 = acc[mi][nj][half_i * 2 + 1];
                size_t idx = idx0 + (size_t)half_i * 8 * HDIM;
                if (z == 2) {
                    __half2 hv = __floats2half2_rn(v0, v1);
                    *reinterpret_cast<__half2*>(Vh + idx) = hv;
                } else {
                    __nv_bfloat16 h0 = __float2bfloat16(v0);
                    __nv_bfloat16 h1 = __float2bfloat16(v1);
                    uint32_t uhi = (uint32_t)__bfloat16_as_ushort(h0) |
                                   ((uint32_t)__bfloat16_as_ushort(h1) << 16);
                    uint32_t ulo = pack_bf16(v0 - __bfloat162float(h0),
                                             v1 - __bfloat162float(h1));
                    *reinterpret_cast<uint32_t*>(OutHi + idx) = uhi;
                    *reinterpret_cast<uint32_t*>(OutLo + idx) = ulo;
                }
            }
        }
    }
}

// ===========================================================================
// Tensor-core flash attention (unchanged from R6 - proven at 206us).
// ===========================================================================
#define AT_SMEM (32768 + 2 * 24576)

__global__ __launch_bounds__(256)
void attn_tc_kernel(const __nv_bfloat16* __restrict__ Qhi,
                    const __nv_bfloat16* __restrict__ Qlo,
                    const __nv_bfloat16* __restrict__ Khi,
                    const __nv_bfloat16* __restrict__ Klo,
                    const __half* __restrict__ Vh,
                    float* __restrict__ Out)
{
    extern __shared__ char sma[];
    const uint32_t sm0 = smem_u32(sma);
    const int tid  = threadIdx.x;
    const int lane = tid & 31;
    const int wq   = tid >> 5;
    const int q0   = blockIdx.x * 128;
    const int h    = blockIdx.y;
    const int b    = blockIdx.z;
    const size_t base = ((size_t)(b * NHEADS + h)) * SEQ * HDIM;

    const uint4* gqh = (const uint4*)(Qhi + base + (size_t)q0 * HDIM);
    const uint4* gql = (const uint4*)(Qlo + base + (size_t)q0 * HDIM);
    const uint4* gkh = (const uint4*)(Khi + base);
    const uint4* gkl = (const uint4*)(Klo + base);
    const uint4* gvh = (const uint4*)(Vh  + base);

    // ---- load Q tile (128 x 64 bf16, hi+lo) into smem
#pragma unroll
    for (int i = 0; i < 4; i++) {
        int lin = tid + i * 256;
        int row = lin >> 3, col = lin & 7;
        uint32_t off = sw128(row * 128 + col * 16);
        *reinterpret_cast<uint4*>(sma + off)         = gqh[row * 8 + col];
        *reinterpret_cast<uint4*>(sma + 16384 + off) = gql[row * 8 + col];
    }

    // K hi (8K) + K lo (8K) + V fp16 (8K) per stage
    auto kv_fill = [&](uint32_t dstbase, int kt) {
#pragma unroll
        for (int i = 0; i < 6; i++) {
            int lin = tid + i * 256;
            int mat = lin >> 9;                 // 0: Khi, 1: Klo, 2: V
            int rem = lin & 511;
            int row = rem >> 3, col = rem & 7;
            const uint4* src =
                (mat == 0 ? gkh : mat == 1 ? gkl : gvh)
                + (size_t)(kt + row) * 8 + col;
            uint32_t dst = dstbase + mat * 8192 + sw128(row * 128 + col * 16);
            CP_A16(dst, src);
        }
    };
    kv_fill(sm0 + 32768, 0);
    CP_COMMIT();

    __syncthreads();   // Q smem ready

    const int rIn    = lane & 7;
    const int a_rsel = ((lane >> 3) & 1) * 8;
    const int a_ksel = ((lane >> 4) & 1) * 16;
    const int b_nsel = ((lane >> 4) & 1) * 8;
    const int b_ksel = ((lane >> 3) & 1) * 16;
    const int v_rsel = ((lane >> 3) & 1) * 8;
    const int v_nsel = ((lane >> 4) & 1) * 16;

    uint32_t qh[4][4], ql[4][4];
#pragma unroll
    for (int ks = 0; ks < 4; ks++) {
        uint32_t off = sw128((wq * 16 + a_rsel + rIn) * 128 + ks * 32 + a_ksel);
        LDSM_X4(qh[ks][0], qh[ks][1], qh[ks][2], qh[ks][3], sm0 + off);
        LDSM_X4(ql[ks][0], ql[ks][1], ql[ks][2], ql[ks][3], sm0 + 16384 + off);
    }

    float o[8][4];
#pragma unroll
    for (int v = 0; v < 8; v++)
#pragma unroll
        for (int e = 0; e < 4; e++) o[v][e] = 0.f;
    float m0r = -3.0e38f, m1r = -3.0e38f;   // log2-domain running max
    float l0 = 0.f, l1 = 0.f;

    for (int t = 0; t < SEQ / 64; t++) {
        if (t + 1 < SEQ / 64) {
            kv_fill(sm0 + 32768 + ((t + 1) & 1) * 24576, (t + 1) * 64);
            CP_COMMIT();
            CP_WAIT(1);
        } else {
            CP_WAIT(0);
        }
        __syncthreads();
        const uint32_t kb = sm0 + 32768 + (t & 1) * 24576;
        const uint32_t vb = kb + 16384;

        // ---- S = Q K^T (3-term bf16 split), raw dot domain
        float s[8][4];
#pragma unroll
        for (int j = 0; j < 8; j++)
#pragma unroll
            for (int e = 0; e < 4; e++) s[j][e] = 0.f;
#pragma unroll
        for (int ks = 0; ks < 4; ks++) {
#pragma unroll
            for (int np = 0; np < 4; np++) {
                uint32_t off = sw128((np * 16 + b_nsel + rIn) * 128 + ks * 32 + b_ksel);
                uint32_t kf[4], lf[4];
                LDSM_X4(kf[0], kf[1], kf[2], kf[3], kb + off);
                LDSM_X4(lf[0], lf[1], lf[2], lf[3], kb + 8192 + off);
                MMA_BF16(s[np * 2],     qh[ks], kf[0], kf[1]);
                MMA_BF16(s[np * 2],     ql[ks], kf[0], kf[1]);
                MMA_BF16(s[np * 2],     qh[ks], lf[0], lf[1]);
                MMA_BF16(s[np * 2 + 1], qh[ks], kf[2], kf[3]);
                MMA_BF16(s[np * 2 + 1], ql[ks], kf[2], kf[3]);
                MMA_BF16(s[np * 2 + 1], qh[ks], lf[2], lf[3]);
            }
        }

        // ---- softmax in exp2 domain: weight = 2^(s*C - M2)
        float mt0 = -3.0e38f, mt1 = -3.0e38f;
#pragma unroll
        for (int j = 0; j < 8; j++) {
            mt0 = fmaxf(mt0, fmaxf(s[j][0], s[j][1]));
            mt1 = fmaxf(mt1, fmaxf(s[j][2], s[j][3]));
        }
        mt0 = fmaxf(mt0, __shfl_xor_sync(0xffffffffu, mt0, 1));
        mt0 = fmaxf(mt0, __shfl_xor_sync(0xffffffffu, mt0, 2));
        mt1 = fmaxf(mt1, __shfl_xor_sync(0xffffffffu, mt1, 1));
        mt1 = fmaxf(mt1, __shfl_xor_sync(0xffffffffu, mt1, 2));
        float M0 = fmaxf(m0r, mt0 * EXP2_SCALE);
        float M1 = fmaxf(m1r, mt1 * EXP2_SCALE);
        float a0 = ex2f(m0r - M0);
        float a1 = ex2f(m1r - M1);
        m0r = M0; m1r = M1;

        float rs0 = 0.f, rs1 = 0.f;
        uint32_t ap[4][4];   // P fragments, fp16
#pragma unroll
        for (int jp = 0; jp < 4; jp++) {
#pragma unroll
            for (int half_i = 0; half_i < 2; half_i++) {
                int j = jp * 2 + half_i;
                float p0 = ex2f(fmaf(s[j][0], EXP2_SCALE, -M0));
                float p1 = ex2f(fmaf(s[j][1], EXP2_SCALE, -M0));
                float p2 = ex2f(fmaf(s[j][2], EXP2_SCALE, -M1));
                float p3 = ex2f(fmaf(s[j][3], EXP2_SCALE, -M1));
                __half2 h01 = __floats2half2_rn(p0, p1);
                __half2 h23 = __floats2half2_rn(p2, p3);
                // l sums the ROUNDED p: quantization cancels in out = (P.V)/l
                float2 f01 = __half22float2(h01);
                float2 f23 = __half22float2(h23);
                rs0 += f01.x + f01.y;
                rs1 += f23.x + f23.y;
                ap[jp][half_i * 2 + 0] = *reinterpret_cast<uint32_t*>(&h01);
                ap[jp][half_i * 2 + 1] = *reinterpret_cast<uint32_t*>(&h23);
            }
        }

        rs0 += __shfl_xor_sync(0xffffffffu, rs0, 1);
        rs0 += __shfl_xor_sync(0xffffffffu, rs0, 2);
        rs1 += __shfl_xor_sync(0xffffffffu, rs1, 1);
        rs1 += __shfl_xor_sync(0xffffffffu, rs1, 2);
        l0 = l0 * a0 + rs0;
        l1 = l1 * a1 + rs1;
#pragma unroll
        for (int v = 0; v < 8; v++) {
            o[v][0] *= a0; o[v][1] *= a0;
            o[v][2] *= a1; o[v][3] *= a1;
        }

        // ---- O += P V (single fp16 term), V via ldmatrix.trans
#pragma unroll
        for (int t4 = 0; t4 < 4; t4++) {
#pragma unroll
            for (int vp = 0; vp < 4; vp++) {
                uint32_t off = sw128((t4 * 16 + v_rsel + rIn) * 128 + vp * 32 + v_nsel);
                uint32_t vf[4];
                LDSM_X4_T(vf[0], vf[1], vf[2], vf[3], vb + off);
                MMA_F16(o[vp * 2],     ap[t4], vf[0], vf[1]);
                MMA_F16(o[vp * 2 + 1], ap[t4], vf[2], vf[3]);
            }
        }
        __syncthreads();   // all reads of this buffer done before refill
    }

    // ---- epilogue: normalize, write out[b][s][h*64+hd]
    float inv0 = 1.f / l0;
    float inv1 = 1.f / l1;
    int s0 = q0 + wq * 16 + (lane >> 2);
    int hd0 = h * 64 + 2 * (lane & 3);
#pragma unroll
    for (int v = 0; v < 8; v++) {
        float2 w0 = make_float2(o[v][0] * inv0, o[v][1] * inv0);
        float2 w1 = make_float2(o[v][2] * inv1, o[v][3] * inv1);
        *reinterpret_cast<float2*>(
            &Out[(size_t)(b * SEQ + s0) * DMODEL + hd0 + v * 8]) = w0;
        *reinterpret_cast<float2*>(
            &Out[(size_t)(b * SEQ + s0 + 8) * DMODEL + hd0 + v * 8]) = w1;
    }
}

// ---------------------------------------------------------------------------
extern "C" void kernel_launch(void* const* d_in, const int* in_sizes, int n_in,
                              void* d_out, int out_size)
{
    const float* q  = (const float*)d_in[0];
    const float* k  = (const float*)d_in[1];
    const float* v  = (const float*)d_in[2];
    const float* Wq = (const float*)d_in[3];
    const float* Wk = (const float*)d_in[4];
    const float* Wv = (const float*)d_in[5];
    float* out = (float*)d_out;

    __nv_bfloat16 *Xhi, *Xlo, *Whi, *Wlo;
    __nv_bfloat16 *Qhi, *Qlo, *Khi, *Klo;
    __half *Vh;
    cudaGetSymbolAddress((void**)&Xhi, g_Xhi);
    cudaGetSymbolAddress((void**)&Xlo, g_Xlo);
    cudaGetSymbolAddress((void**)&Whi, g_Whi);
    cudaGetSymbolAddress((void**)&Wlo, g_Wlo);
    cudaGetSymbolAddress((void**)&Qhi, g_Qhi);
    cudaGetSymbolAddress((void**)&Qlo, g_Qlo);
    cudaGetSymbolAddress((void**)&Khi, g_Khi);
    cudaGetSymbolAddress((void**)&Klo, g_Klo);
    cudaGetSymbolAddress((void**)&Vh,  g_Vh);

    cudaFuncSetAttribute(proj_mma_kernel,
                         cudaFuncAttributeMaxDynamicSharedMemorySize, PROJ_SMEM);
    cudaFuncSetAttribute(attn_tc_kernel,
                         cudaFuncAttributeMaxDynamicSharedMemorySize, AT_SMEM);

    const int nX4 = 4096 * 1024 / 4;
    const int nW4 = 1024 * 1024 / 4;
    split_kernel<<<nX4 / 256, 256>>>((const float4*)q, Xhi,               Xlo,               nX4);
    split_kernel<<<nX4 / 256, 256>>>((const float4*)k, Xhi + 4194304,     Xlo + 4194304,     nX4);
    split_kernel<<<nX4 / 256, 256>>>((const float4*)v, Xhi + 2 * 4194304, Xlo + 2 * 4194304, nX4);
    split_kernel<<<nW4 / 256, 256>>>((const float4*)Wq, Whi,               Wlo,               nW4);
    split_kernel<<<nW4 / 256, 256>>>((const float4*)Wk, Whi + 1048576,     Wlo + 1048576,     nW4);
    split_kernel<<<nW4 / 256, 256>>>((const float4*)Wv, Whi + 2 * 1048576, Wlo + 2 * 1048576, nW4);

    dim3 pg(4096 / 128, 1024 / 128, 3);
    proj_mma_kernel<<<pg, 256, PROJ_SMEM>>>(Xhi, Xlo, Whi, Wlo,
                                            Qhi, Qlo, Khi, Klo, Vh);

    dim3 ag(SEQ / 128, NHEADS, BATCH);   // (16, 16, 2)
    attn_tc_kernel<<<ag, 256, AT_SMEM>>>(Qhi, Qlo, Khi, Klo, Vh, out);
}